// round 7
// baseline (speedup 1.0000x reference)
#include <cuda_runtime.h>
#include <cstdint>

#define NB    4
#define SEQ   2048
#define DIM   1024
#define HEADS 8
#define HD    128
#define MROWS (NB*SEQ)

// Scratch (device globals — no allocation allowed)
__device__ float g_v  [(size_t)NB*HEADS*SEQ*HD];
__device__ float g_ek [(size_t)NB*HEADS*SEQ*HD];
__device__ float g_ekv[(size_t)NB*HEADS*SEQ*HD];
__device__ float g_aft[(size_t)MROWS*DIM];
__device__ float g_xr [(size_t)MROWS*DIM];     // tf32-rounded x
__device__ float g_wkr[(size_t)DIM*DIM];       // tf32-rounded weights [k][n]
__device__ float g_wvr[(size_t)DIM*DIM];
__device__ float g_wor[(size_t)DIM*DIM];

#define MODE_V   0
#define MODE_K   1
#define MODE_OUT 2

__device__ __forceinline__ uint32_t f2tf32(float x) {
    uint32_t r;
    asm("cvt.rna.tf32.f32 %0, %1;" : "=r"(r) : "f"(x));
    return r;
}
__device__ __forceinline__ float f2tf32f(float x) {
    return __uint_as_float(f2tf32(x));
}

__device__ __forceinline__ void mma_tf32(float c[4],
    uint32_t a0, uint32_t a1, uint32_t a2, uint32_t a3,
    uint32_t b0, uint32_t b1)
{
    asm volatile(
        "mma.sync.aligned.m16n8k8.row.col.f32.tf32.tf32.f32 "
        "{%0,%1,%2,%3}, {%4,%5,%6,%7}, {%8,%9}, {%0,%1,%2,%3};\n"
        : "+f"(c[0]), "+f"(c[1]), "+f"(c[2]), "+f"(c[3])
        : "r"(a0), "r"(a1), "r"(a2), "r"(a3), "r"(b0), "r"(b1));
}

__device__ __forceinline__ uint32_t smem_u32(const void* p) {
    return (uint32_t)__cvta_generic_to_shared(p);
}
__device__ __forceinline__ void cp16(uint32_t dst, const void* src) {
    asm volatile("cp.async.ca.shared.global [%0], [%1], 16;\n" :: "r"(dst), "l"(src));
}
__device__ __forceinline__ void cp_commit() {
    asm volatile("cp.async.commit_group;\n");
}
__device__ __forceinline__ void cp_wait2() {
    asm volatile("cp.async.wait_group 2;\n");
}

// ---------------------------------------------------------------------------
// prep: tf32-round x and the three weight matrices into scratch.
// ---------------------------------------------------------------------------
__global__ __launch_bounds__(256)
void prep_round(const float4* __restrict__ x, const float4* __restrict__ wk,
                const float4* __restrict__ wv, const float4* __restrict__ wo)
{
    const size_t X4 = (size_t)MROWS * DIM / 4;
    size_t i = (size_t)blockIdx.x * blockDim.x + threadIdx.x;
    const float4* src;
    float4* dst;
    if (i < X4) {
        src = x + i;
        dst = (float4*)g_xr + i;
    } else {
        size_t j = i - X4;
        int seg = (int)(j >> 18);
        size_t o = j & ((1u << 18) - 1);
        src = (seg == 0 ? wk : (seg == 1 ? wv : wo)) + o;
        dst = (float4*)(seg == 0 ? g_wkr : (seg == 1 ? g_wvr : g_wor)) + o;
    }
    float4 v = *src;
    float4 r;
    r.x = f2tf32f(v.x); r.y = f2tf32f(v.y);
    r.z = f2tf32f(v.z); r.w = f2tf32f(v.w);
    *dst = r;
}

// ---------------------------------------------------------------------------
// GEMM: C[8192,1024] = A @ B + bias. Block 128x128, BK=16, 512 threads,
// warps 4(m) x 4(n), warp tile 32x32 (acc 32 regs). 4-stage cp.async.
// ---------------------------------------------------------------------------
#define A_STRIDE 20
#define B_STRIDE 136
#define A_STG (128*A_STRIDE)
#define B_STG (16*B_STRIDE)
#define B_OFF (4*A_STG)
#define GEMM_SMEM_B ((4*A_STG + 4*B_STG)*4)   // 75776 bytes

template<int MODE>
__global__ __launch_bounds__(512, 2)
void gemm_tc(const float* __restrict__ bias, float* __restrict__ out)
{
    extern __shared__ uint32_t sm[];

    const float* A = (MODE == MODE_OUT) ? g_aft : g_xr;
    const float* B = (MODE == MODE_V) ? g_wvr : (MODE == MODE_K ? g_wkr : g_wor);

    const int tid  = threadIdx.x;
    const int lane = tid & 31;
    const int warp = tid >> 5;       // 0..15
    const int wm   = warp >> 2;      // 0..3
    const int wn   = warp & 3;       // 0..3
    const int r    = lane >> 2;
    const int cc   = lane & 3;

    const int bm = blockIdx.y << 7;
    const int bn = blockIdx.x << 7;

    // loads: 512 A-float4 + 512 B-float4 per stage, 1 each per thread
    const int am  = tid >> 2;              // 0..127
    const int ak4 = (tid & 3) << 2;
    const int bk_ = tid >> 5;              // 0..15
    const int bn4 = (tid & 31) << 2;

    const float* Abase = A + (size_t)bm * DIM;
    const float* Bbase = B + bn;

    const uint32_t aAddr = smem_u32(&sm[am * A_STRIDE + ak4]);
    const uint32_t bAddr = smem_u32(&sm[B_OFF + bk_ * B_STRIDE + bn4]);

    auto issue = [&](int k0, int st) {
        cp16(aAddr + st * (A_STG * 4), Abase + (size_t)am * DIM + k0 + ak4);
        cp16(bAddr + st * (B_STG * 4), Bbase + (size_t)(k0 + bk_) * DIM + bn4);
        cp_commit();
    };

    float acc[2][4][4] = {};

    issue(0, 0); issue(16, 1); issue(32, 2);

    const int NT = DIM / 16;   // 64
    const int m0b = wm << 5;
    const int n0b = wn << 5;

    for (int kt = 0; kt < NT; kt++) {
        const int buf = kt & 3;
        cp_wait2();
        __syncthreads();
        if (kt + 3 < NT) issue((kt + 3) << 4, (kt + 3) & 3);
        else cp_commit();

        const uint32_t* Ab = sm + buf * A_STG;
        const uint32_t* Bb = sm + B_OFF + buf * B_STG;

        #pragma unroll
        for (int ks = 0; ks < 2; ks++) {
            const int k8 = ks << 3;
            uint32_t af[2][4], bf[4][2];
            #pragma unroll
            for (int im = 0; im < 2; im++) {
                const int m0 = m0b + (im << 4);
                af[im][0] = Ab[(m0 + r    ) * A_STRIDE + k8 + cc    ];
                af[im][1] = Ab[(m0 + r + 8) * A_STRIDE + k8 + cc    ];
                af[im][2] = Ab[(m0 + r    ) * A_STRIDE + k8 + cc + 4];
                af[im][3] = Ab[(m0 + r + 8) * A_STRIDE + k8 + cc + 4];
            }
            #pragma unroll
            for (int in = 0; in < 4; in++) {
                const int n0 = n0b + (in << 3);
                bf[in][0] = Bb[(k8 + cc    ) * B_STRIDE + n0 + r];
                bf[in][1] = Bb[(k8 + cc + 4) * B_STRIDE + n0 + r];
            }
            #pragma unroll
            for (int im = 0; im < 2; im++)
                #pragma unroll
                for (int in = 0; in < 4; in++)
                    mma_tf32(acc[im][in], af[im][0], af[im][1], af[im][2], af[im][3],
                             bf[in][0], bf[in][1]);
        }
    }

    #pragma unroll
    for (int im = 0; im < 2; im++) {
        #pragma unroll
        for (int in = 0; in < 4; in++) {
            #pragma unroll
            for (int e = 0; e < 4; e++) {
                const int row = bm + m0b + (im << 4) + r + ((e >> 1) << 3);
                const int col = bn + n0b + (in << 3) + (cc << 1) + (e & 1);
                const float val = acc[im][in][e] + bias[col];
                if (MODE == MODE_OUT) {
                    out[(size_t)row * DIM + col] = val;
                } else {
                    const int n = row >> 11, s = row & (SEQ - 1);
                    const int h = col >> 7, d = col & 127;
                    const size_t idx = (((size_t)(n * HEADS + h)) * SEQ + s) * HD + d;
                    if (MODE == MODE_V) {
                        g_v[idx] = val;
                    } else {
                        const float ek = __expf(val);
                        g_ek[idx]  = f2tf32f(ek);
                        g_ekv[idx] = f2tf32f(ek * g_v[idx]);
                    }
                }
            }
        }
    }
}

// ---------------------------------------------------------------------------
// AFT core: block 64t x 128d, 512 threads, warps 4(t) x 4(d), warp tile 16x32
// (accN+accD = 32 regs). s-chunks of 16, 4-stage cp.async for ek/ekv,
// 2-slot reg-prefetched exp(w). Heavy-first.
// ---------------------------------------------------------------------------
#define W_STRIDE 20
#define W_STG (64*W_STRIDE)
#define E_OFF (2*W_STG)
#define E_STG (16*B_STRIDE)
#define EV_OFF (E_OFF + 4*E_STG)
#define AFT_SMEM_B ((EV_OFF + 4*E_STG)*4)     // 79872 bytes

__global__ __launch_bounds__(512, 2)
void aft_tc(const float* __restrict__ w_aft)
{
    extern __shared__ uint32_t sm[];

    const int tid  = threadIdx.x;
    const int lane = tid & 31;
    const int warp = tid >> 5;       // 0..15
    const int wm   = warp >> 2;      // 0..3 over t
    const int wn   = warp & 3;       // 0..3 over d
    const int r    = lane >> 2;
    const int cc   = lane & 3;

    const int bt = gridDim.x - 1 - blockIdx.x;   // heavy tiles first
    const int t0 = bt << 6;
    const int nh = blockIdx.y;
    const int n  = nh >> 3;
    const int h  = nh & 7;

    const float* wbase  = w_aft + ((size_t)h * SEQ + t0) * SEQ;
    const float* ekbase = g_ek  + (size_t)nh * SEQ * HD;
    const float* evbase = g_ekv + (size_t)nh * SEQ * HD;

    // w: 256 float4 per chunk -> threads 0..255
    const int w_tl = tid >> 2;           // 0..127 (only <64 used)
    const int w_s4 = (tid & 3) << 2;
    const bool wact = tid < 256;
    // ek/ekv: 512 float4 each per chunk -> 1 per thread
    const int e_sl = tid >> 5;           // 0..15
    const int e_d4 = (tid & 31) << 2;

    const uint32_t ekAddr = smem_u32(&sm[E_OFF  + e_sl * B_STRIDE + e_d4]);
    const uint32_t evAddr = smem_u32(&sm[EV_OFF + e_sl * B_STRIDE + e_d4]);

    auto issueE = [&](int s0, int st) {
        const uint32_t eo = st * (E_STG * 4);
        cp16(ekAddr + eo, ekbase + (size_t)(s0 + e_sl) * HD + e_d4);
        cp16(evAddr + eo, evbase + (size_t)(s0 + e_sl) * HD + e_d4);
        cp_commit();
    };

    uint32_t wv[4];
    auto loadW = [&](int s0) {
        if (wact) {
            float4 w4 = *(const float4*)(wbase + (size_t)w_tl * SEQ + s0 + w_s4);
            const int tg = t0 + w_tl;
            wv[0] = (s0 + w_s4 + 0 <= tg) ? f2tf32(__expf(w4.x)) : 0u;
            wv[1] = (s0 + w_s4 + 1 <= tg) ? f2tf32(__expf(w4.y)) : 0u;
            wv[2] = (s0 + w_s4 + 2 <= tg) ? f2tf32(__expf(w4.z)) : 0u;
            wv[3] = (s0 + w_s4 + 3 <= tg) ? f2tf32(__expf(w4.w)) : 0u;
        }
    };
    auto storeW = [&](int slot) {
        if (wact) {
            uint4 u = { wv[0], wv[1], wv[2], wv[3] };
            *(uint4*)(sm + slot * W_STG + w_tl * W_STRIDE + w_s4) = u;
        }
    };

    float accN[4][4] = {};
    float accD[4][4] = {};

    const int nch = (bt + 1) << 2;
    loadW(0);
    issueE(0, 0); issueE(16, 1); issueE(32, 2);

    const int m0b = wm << 4;
    const int n0b = wn << 5;

    for (int c = 0; c < nch; c++) {
        const int wslot = c & 1;
        const int ebuf  = c & 3;
        storeW(wslot);
        cp_wait2();
        __syncthreads();
        if (c + 3 < nch) issueE((c + 3) << 4, (c + 3) & 3);
        else cp_commit();
        if (c + 1 < nch) loadW((c + 1) << 4);

        const uint32_t* Wb = sm + wslot * W_STG;
        const uint32_t* Kb = sm + E_OFF  + ebuf * E_STG;
        const uint32_t* Vb = sm + EV_OFF + ebuf * E_STG;

        #pragma unroll
        for (int ks = 0; ks < 2; ks++) {
            const int k8 = ks << 3;
            uint32_t af[4], bk[4][2], bv[4][2];
            af[0] = Wb[(m0b + r    ) * W_STRIDE + k8 + cc    ];
            af[1] = Wb[(m0b + r + 8) * W_STRIDE + k8 + cc    ];
            af[2] = Wb[(m0b + r    ) * W_STRIDE + k8 + cc + 4];
            af[3] = Wb[(m0b + r + 8) * W_STRIDE + k8 + cc + 4];
            #pragma unroll
            for (int in = 0; in < 4; in++) {
                const int n0 = n0b + (in << 3);
                bk[in][0] = Kb[(k8 + cc    ) * B_STRIDE + n0 + r];
                bk[in][1] = Kb[(k8 + cc + 4) * B_STRIDE + n0 + r];
                bv[in][0] = Vb[(k8 + cc    ) * B_STRIDE + n0 + r];
                bv[in][1] = Vb[(k8 + cc + 4) * B_STRIDE + n0 + r];
            }
            #pragma unroll
            for (int in = 0; in < 4; in++) {
                mma_tf32(accN[in], af[0], af[1], af[2], af[3], bv[in][0], bv[in][1]);
                mma_tf32(accD[in], af[0], af[1], af[2], af[3], bk[in][0], bk[in][1]);
            }
        }
        __syncthreads();
    }

    #pragma unroll
    for (int in = 0; in < 4; in++) {
        #pragma unroll
        for (int e = 0; e < 4; e++) {
            const int t = t0 + m0b + r + ((e >> 1) << 3);
            const int d = n0b + (in << 3) + (cc << 1) + (e & 1);
            g_aft[((size_t)(n * SEQ + t)) * DIM + h * HD + d] =
                f2tf32f(accN[in][e] / accD[in][e]);
        }
    }
}

extern "C" void kernel_launch(void* const* d_in, const int* in_sizes, int n_in,
                              void* d_out, int out_size)
{
    const float* x     = (const float*)d_in[0];
    const float* Wk    = (const float*)d_in[1];
    const float* bk    = (const float*)d_in[2];
    const float* Wv    = (const float*)d_in[3];
    const float* bv    = (const float*)d_in[4];
    const float* w_aft = (const float*)d_in[5];
    const float* Wo    = (const float*)d_in[6];
    const float* bo    = (const float*)d_in[7];
    float* out = (float*)d_out;

    cudaFuncSetAttribute(gemm_tc<MODE_V>,   cudaFuncAttributeMaxDynamicSharedMemorySize, GEMM_SMEM_B);
    cudaFuncSetAttribute(gemm_tc<MODE_K>,   cudaFuncAttributeMaxDynamicSharedMemorySize, GEMM_SMEM_B);
    cudaFuncSetAttribute(gemm_tc<MODE_OUT>, cudaFuncAttributeMaxDynamicSharedMemorySize, GEMM_SMEM_B);
    cudaFuncSetAttribute(aft_tc,            cudaFuncAttributeMaxDynamicSharedMemorySize, AFT_SMEM_B);

    prep_round<<<11264, 256>>>((const float4*)x, (const float4*)Wk,
                               (const float4*)Wv, (const float4*)Wo);

    dim3 gg(DIM / 128, MROWS / 128);   // (8, 64)
    gemm_tc<MODE_V><<<gg, 512, GEMM_SMEM_B>>>(bv, nullptr);
    gemm_tc<MODE_K><<<gg, 512, GEMM_SMEM_B>>>(bk, nullptr);
    aft_tc<<<dim3(SEQ / 64, NB * HEADS), 512, AFT_SMEM_B>>>(w_aft);
    gemm_tc<MODE_OUT><<<gg, 512, GEMM_SMEM_B>>>(bo, out);
}

// round 9
// speedup vs baseline: 1.8651x; 1.8651x over previous
#include <cuda_runtime.h>
#include <cuda_fp16.h>
#include <cstdint>

#define NB    4
#define SEQ   2048
#define DIM   1024
#define HEADS 8
#define HD    128
#define MROWS (NB*SEQ)

// Scratch (device globals — no allocation allowed)
__device__ float  g_v   [(size_t)NB*HEADS*SEQ*HD];     // V projection (fp32)
__device__ __half g_ekh [(size_t)NB*HEADS*SEQ*HD];     // exp(k), half
__device__ __half g_ekvh[(size_t)NB*HEADS*SEQ*HD];     // exp(k)*v, half
__device__ __half g_afth[(size_t)MROWS*DIM];           // AFT output, half
__device__ __half g_xh  [(size_t)MROWS*DIM];           // x, half
__device__ __half g_wkh [(size_t)DIM*DIM];             // weights [k][n], half
__device__ __half g_wvh [(size_t)DIM*DIM];
__device__ __half g_woh [(size_t)DIM*DIM];

#define MODE_V   0
#define MODE_K   1
#define MODE_OUT 2

// ---------------------------------------------------------------------------
// helpers
// ---------------------------------------------------------------------------
__device__ __forceinline__ void mma_f16(float c[4],
    uint32_t a0, uint32_t a1, uint32_t a2, uint32_t a3,
    uint32_t b0, uint32_t b1)
{
    asm volatile(
        "mma.sync.aligned.m16n8k16.row.col.f32.f16.f16.f32 "
        "{%0,%1,%2,%3}, {%4,%5,%6,%7}, {%8,%9}, {%0,%1,%2,%3};\n"
        : "+f"(c[0]), "+f"(c[1]), "+f"(c[2]), "+f"(c[3])
        : "r"(a0), "r"(a1), "r"(a2), "r"(a3), "r"(b0), "r"(b1));
}

__device__ __forceinline__ void ldsm_x4(uint32_t r[4], uint32_t addr) {
    asm volatile("ldmatrix.sync.aligned.m8n8.x4.shared.b16 {%0,%1,%2,%3}, [%4];\n"
        : "=r"(r[0]), "=r"(r[1]), "=r"(r[2]), "=r"(r[3]) : "r"(addr));
}
__device__ __forceinline__ void ldsm_x4_t(uint32_t r[4], uint32_t addr) {
    asm volatile("ldmatrix.sync.aligned.m8n8.x4.trans.shared.b16 {%0,%1,%2,%3}, [%4];\n"
        : "=r"(r[0]), "=r"(r[1]), "=r"(r[2]), "=r"(r[3]) : "r"(addr));
}

__device__ __forceinline__ uint32_t smem_u32(const void* p) {
    return (uint32_t)__cvta_generic_to_shared(p);
}
__device__ __forceinline__ void cp16(uint32_t dst, const void* src) {
    asm volatile("cp.async.ca.shared.global [%0], [%1], 16;\n" :: "r"(dst), "l"(src));
}
__device__ __forceinline__ void cp_commit() {
    asm volatile("cp.async.commit_group;\n");
}
__device__ __forceinline__ void cp_wait2() {
    asm volatile("cp.async.wait_group 2;\n");
}

__device__ __forceinline__ uint32_t pack_h2(float a, float b) {
    __half2 h = __floats2half2_rn(a, b);
    return *reinterpret_cast<uint32_t*>(&h);
}

// ---------------------------------------------------------------------------
// prep: round x + 3 weights to fp16. Each thread: 8 floats -> 8 halfs (16B).
// ---------------------------------------------------------------------------
__global__ __launch_bounds__(256)
void prep_h(const float4* __restrict__ x, const float4* __restrict__ wk,
            const float4* __restrict__ wv, const float4* __restrict__ wo)
{
    const size_t X8 = (size_t)MROWS * DIM / 8;    // 1048576
    const size_t W8 = (size_t)DIM * DIM / 8;      // 131072
    size_t i = (size_t)blockIdx.x * 256 + threadIdx.x;
    const float4* src;
    uint4* dst;
    if (i < X8) {
        src = x + i * 2;
        dst = (uint4*)g_xh + i;
    } else {
        size_t j = i - X8;
        int seg = (int)(j / W8);
        size_t o = j % W8;
        src = (seg == 0 ? wk : (seg == 1 ? wv : wo)) + o * 2;
        dst = (uint4*)(seg == 0 ? g_wkh : (seg == 1 ? g_wvh : g_woh)) + o;
    }
    float4 a = src[0], b = src[1];
    uint4 u;
    u.x = pack_h2(a.x, a.y); u.y = pack_h2(a.z, a.w);
    u.z = pack_h2(b.x, b.y); u.w = pack_h2(b.z, b.w);
    *dst = u;
}

// ---------------------------------------------------------------------------
// GEMM: C[8192,1024] = A @ W + bias, fp16 mma + ldmatrix.
// Block 128x128, BK=32, 512 threads, warps 4(m)x4(n), warp tile 32x32.
// A smem [m][k] rows 80B; W smem [k][n] rows 272B. 4-stage cp.async.
// ---------------------------------------------------------------------------
#define A_ROWB 80
#define B_ROWB 272
#define A_STGB (128*A_ROWB)            // 10240
#define B_STGB (32*B_ROWB)             // 8704
#define B_OFFB (4*A_STGB)              // 40960
#define GEMM_SMEM_B (4*A_STGB + 4*B_STGB)   // 75776

template<int MODE>
__global__ __launch_bounds__(512, 2)
void gemm_h(const float* __restrict__ bias, float* __restrict__ out)
{
    extern __shared__ char smc[];
    const uint32_t sb = smem_u32(smc);

    const __half* A = (MODE == MODE_OUT) ? g_afth : g_xh;
    const __half* W = (MODE == MODE_V) ? g_wvh : (MODE == MODE_K ? g_wkh : g_woh);

    const int tid  = threadIdx.x;
    const int lane = tid & 31;
    const int warp = tid >> 5;
    const int wm   = warp >> 2;
    const int wn   = warp & 3;
    const int r    = lane >> 2;
    const int cc   = lane & 3;

    const int bm = blockIdx.y << 7;
    const int bn = blockIdx.x << 7;

    // cp.async: A 512 chunks (128 rows x 4), B 512 chunks (32 rows x 16); 1+1 per thread
    const int am  = tid >> 2;            // 0..127
    const int ac8 = (tid & 3) << 3;      // half idx 0,8,16,24
    const int bkr = tid >> 4;            // 0..31
    const int bc8 = (tid & 15) << 3;     // half idx 0..120

    const __half* Abase = A + (size_t)bm * DIM;
    const __half* Wbase = W + bn;

    const uint32_t aAddr = sb + am * A_ROWB + ac8 * 2;
    const uint32_t bAddr = sb + B_OFFB + bkr * B_ROWB + bc8 * 2;

    auto issue = [&](int c) {
        const int st = c & 3;
        const int k0 = c << 5;
        cp16(aAddr + st * A_STGB, Abase + (size_t)am * DIM + k0 + ac8);
        cp16(bAddr + st * B_STGB, Wbase + (size_t)(k0 + bkr) * DIM + bc8);
        cp_commit();
    };

    float acc[2][4][4] = {};

    issue(0); issue(1); issue(2);

    // ldmatrix per-thread row offsets
    const int lrow = lane & 15;
    const int lk8  = (lane >> 4) << 3;

    const int NCH = DIM / 32;   // 32
    for (int c = 0; c < NCH; c++) {
        const int st = c & 3;
        cp_wait2();
        __syncthreads();
        if (c + 3 < NCH) issue(c + 3);
        else cp_commit();

        const uint32_t Abuf = sb + st * A_STGB;
        const uint32_t Bbuf = sb + B_OFFB + st * B_STGB;

        #pragma unroll
        for (int ks = 0; ks < 2; ks++) {
            const int k0h = ks << 4;
            uint32_t af[2][4], bf[2][4];
            #pragma unroll
            for (int im = 0; im < 2; im++) {
                const int m0 = (wm << 5) + (im << 4);
                ldsm_x4(af[im], Abuf + (m0 + lrow) * A_ROWB + (k0h + lk8) * 2);
            }
            #pragma unroll
            for (int ng = 0; ng < 2; ng++) {
                const int n0 = (wn << 5) + (ng << 4);
                ldsm_x4_t(bf[ng], Bbuf + (k0h + lrow) * B_ROWB + (n0 + lk8) * 2);
            }
            #pragma unroll
            for (int im = 0; im < 2; im++)
                #pragma unroll
                for (int ng = 0; ng < 2; ng++) {
                    mma_f16(acc[im][2*ng],   af[im][0], af[im][1], af[im][2], af[im][3],
                            bf[ng][0], bf[ng][1]);
                    mma_f16(acc[im][2*ng+1], af[im][0], af[im][1], af[im][2], af[im][3],
                            bf[ng][2], bf[ng][3]);
                }
        }
    }

    // epilogue (m16n8 C layout: c0,c1 row r cols 2cc,2cc+1; c2,c3 row r+8)
    #pragma unroll
    for (int im = 0; im < 2; im++) {
        #pragma unroll
        for (int in = 0; in < 4; in++) {
            #pragma unroll
            for (int e = 0; e < 4; e++) {
                const int row = bm + (wm << 5) + (im << 4) + r + ((e >> 1) << 3);
                const int col = bn + (wn << 5) + (in << 3) + (cc << 1) + (e & 1);
                const float val = acc[im][in][e] + bias[col];
                if (MODE == MODE_OUT) {
                    out[(size_t)row * DIM + col] = val;
                } else {
                    const int n = row >> 11, s = row & (SEQ - 1);
                    const int h = col >> 7, d = col & 127;
                    const size_t idx = (((size_t)(n * HEADS + h)) * SEQ + s) * HD + d;
                    if (MODE == MODE_V) {
                        g_v[idx] = val;
                    } else {
                        const float ek = __expf(val);
                        g_ekh[idx]  = __float2half_rn(ek);
                        g_ekvh[idx] = __float2half_rn(ek * g_v[idx]);
                    }
                }
            }
        }
    }
}

// ---------------------------------------------------------------------------
// AFT core, fp16 mma + ldmatrix. Block 64t x 128d, 512 threads,
// warps 4(t)x4(d), warp tile 16x32, s-chunks of 32, causal, heavy-first.
// W tile [t][s] rows 80B (2 slots); ek/ekv [s][d] rows 272B (4 stages).
// ---------------------------------------------------------------------------
#define W_STGB  (64*A_ROWB)            // 5120
#define E_OFFB  (2*W_STGB)             // 10240
#define E_STGB  (32*B_ROWB)            // 8704
#define EV_OFFB (E_OFFB + 4*E_STGB)    // 45056
#define AFT_SMEM_B (EV_OFFB + 4*E_STGB)   // 79872

__global__ __launch_bounds__(512, 2)
void aft_h(const float* __restrict__ w_aft)
{
    extern __shared__ char smc[];
    const uint32_t sb = smem_u32(smc);

    const int tid  = threadIdx.x;
    const int lane = tid & 31;
    const int warp = tid >> 5;
    const int wm   = warp >> 2;        // t
    const int wn   = warp & 3;         // d
    const int r    = lane >> 2;
    const int cc   = lane & 3;

    const int bt = gridDim.x - 1 - blockIdx.x;
    const int t0 = bt << 6;
    const int nh = blockIdx.y;
    const int n  = nh >> 3;
    const int h  = nh & 7;

    const float*  wbase  = w_aft  + ((size_t)h * SEQ + t0) * SEQ;
    const __half* ekbase = g_ekh  + (size_t)nh * SEQ * HD;
    const __half* evbase = g_ekvh + (size_t)nh * SEQ * HD;

    // w: 64x32 floats per chunk = 2048; 512 thr x float4
    const int w_tl = tid >> 3;           // 0..63
    const int w_s4 = (tid & 7) << 2;     // 0..28
    // ek/ekv: 32 rows x 16 chunks = 512; 1 each per thread
    const int e_sl = tid >> 4;           // 0..31
    const int e_d8 = (tid & 15) << 3;

    const uint32_t ekAddr = sb + E_OFFB  + e_sl * B_ROWB + e_d8 * 2;
    const uint32_t evAddr = sb + EV_OFFB + e_sl * B_ROWB + e_d8 * 2;

    auto issueE = [&](int c) {
        const int st = c & 3;
        const int s0 = c << 5;
        cp16(ekAddr + st * E_STGB, ekbase + (size_t)(s0 + e_sl) * HD + e_d8);
        cp16(evAddr + st * E_STGB, evbase + (size_t)(s0 + e_sl) * HD + e_d8);
        cp_commit();
    };

    uint32_t wv2[2];
    auto loadW = [&](int s0) {
        float4 w4 = *(const float4*)(wbase + (size_t)w_tl * SEQ + s0 + w_s4);
        const int tg = t0 + w_tl;
        float e0 = (s0 + w_s4 + 0 <= tg) ? __expf(w4.x) : 0.f;
        float e1 = (s0 + w_s4 + 1 <= tg) ? __expf(w4.y) : 0.f;
        float e2 = (s0 + w_s4 + 2 <= tg) ? __expf(w4.z) : 0.f;
        float e3 = (s0 + w_s4 + 3 <= tg) ? __expf(w4.w) : 0.f;
        wv2[0] = pack_h2(e0, e1);
        wv2[1] = pack_h2(e2, e3);
    };
    auto storeW = [&](int slot) {
        *(uint2*)(smc + slot * W_STGB + w_tl * A_ROWB + w_s4 * 2) =
            make_uint2(wv2[0], wv2[1]);
    };

    float accN[4][4] = {};
    float accD[4][4] = {};

    const int nch = (bt + 1) << 1;    // s-chunks of 32 through diagonal
    loadW(0);
    issueE(0); issueE(1); issueE(2);

    const int lrow = lane & 15;
    const int lk8  = (lane >> 4) << 3;
    const int m0b  = wm << 4;

    for (int c = 0; c < nch; c++) {
        const int wslot = c & 1;
        const int ebuf  = c & 3;
        storeW(wslot);
        cp_wait2();
        __syncthreads();
        if (c + 3 < nch) issueE(c + 3);
        else cp_commit();
        if (c + 1 < nch) loadW((c + 1) << 5);

        const uint32_t Wbuf = sb + wslot * W_STGB;
        const uint32_t Kbuf = sb + E_OFFB  + ebuf * E_STGB;
        const uint32_t Vbuf = sb + EV_OFFB + ebuf * E_STGB;

        #pragma unroll
        for (int ks = 0; ks < 2; ks++) {
            const int k0h = ks << 4;
            uint32_t af[4], bk[2][4], bv[2][4];
            ldsm_x4(af, Wbuf + (m0b + lrow) * A_ROWB + (k0h + lk8) * 2);
            #pragma unroll
            for (int ng = 0; ng < 2; ng++) {
                const int n0 = (wn << 5) + (ng << 4);
                ldsm_x4_t(bk[ng], Kbuf + (k0h + lrow) * B_ROWB + (n0 + lk8) * 2);
                ldsm_x4_t(bv[ng], Vbuf + (k0h + lrow) * B_ROWB + (n0 + lk8) * 2);
            }
            #pragma unroll
            for (int ng = 0; ng < 2; ng++) {
                mma_f16(accN[2*ng],   af[0], af[1], af[2], af[3], bv[ng][0], bv[ng][1]);
                mma_f16(accN[2*ng+1], af[0], af[1], af[2], af[3], bv[ng][2], bv[ng][3]);
                mma_f16(accD[2*ng],   af[0], af[1], af[2], af[3], bk[ng][0], bk[ng][1]);
                mma_f16(accD[2*ng+1], af[0], af[1], af[2], af[3], bk[ng][2], bk[ng][3]);
            }
        }
        __syncthreads();
    }

    #pragma unroll
    for (int in = 0; in < 4; in++) {
        #pragma unroll
        for (int e = 0; e < 4; e++) {
            const int t = t0 + m0b + r + ((e >> 1) << 3);
            const int d = (wn << 5) + (in << 3) + (cc << 1) + (e & 1);
            g_afth[((size_t)(n * SEQ + t)) * DIM + h * HD + d] =
                __float2half_rn(accN[in][e] / accD[in][e]);
        }
    }
}

extern "C" void kernel_launch(void* const* d_in, const int* in_sizes, int n_in,
                              void* d_out, int out_size)
{
    const float* x     = (const float*)d_in[0];
    const float* Wk    = (const float*)d_in[1];
    const float* bk    = (const float*)d_in[2];
    const float* Wv    = (const float*)d_in[3];
    const float* bv    = (const float*)d_in[4];
    const float* w_aft = (const float*)d_in[5];
    const float* Wo    = (const float*)d_in[6];
    const float* bo    = (const float*)d_in[7];
    float* out = (float*)d_out;

    cudaFuncSetAttribute(gemm_h<MODE_V>,   cudaFuncAttributeMaxDynamicSharedMemorySize, GEMM_SMEM_B);
    cudaFuncSetAttribute(gemm_h<MODE_K>,   cudaFuncAttributeMaxDynamicSharedMemorySize, GEMM_SMEM_B);
    cudaFuncSetAttribute(gemm_h<MODE_OUT>, cudaFuncAttributeMaxDynamicSharedMemorySize, GEMM_SMEM_B);
    cudaFuncSetAttribute(aft_h,            cudaFuncAttributeMaxDynamicSharedMemorySize, AFT_SMEM_B);

    prep_h<<<5632, 256>>>((const float4*)x, (const float4*)Wk,
                          (const float4*)Wv, (const float4*)Wo);

    dim3 gg(DIM / 128, MROWS / 128);   // (8, 64)
    gemm_h<MODE_V><<<gg, 512, GEMM_SMEM_B>>>(bv, nullptr);
    gemm_h<MODE_K><<<gg, 512, GEMM_SMEM_B>>>(bk, nullptr);
    aft_h<<<dim3(SEQ / 64, NB * HEADS), 512, AFT_SMEM_B>>>(w_aft);
    gemm_h<MODE_OUT><<<gg, 512, GEMM_SMEM_B>>>(bo, out);
}

// round 10
// speedup vs baseline: 2.1626x; 1.1595x over previous
#include <cuda_runtime.h>
#include <cuda_fp16.h>
#include <cstdint>

#define NB    4
#define SEQ   2048
#define DIM   1024
#define HEADS 8
#define HD    128
#define MROWS (NB*SEQ)

// Scratch (device globals — no allocation allowed)
__device__ __half g_ekh [(size_t)NB*HEADS*SEQ*HD];     // exp(k), half
__device__ __half g_ekvh[(size_t)NB*HEADS*SEQ*HD];     // exp(k)*v, half
__device__ __half g_afth[(size_t)MROWS*DIM];           // AFT output, half
__device__ __half g_xh  [(size_t)MROWS*DIM];           // x, half
__device__ __half g_wkh [(size_t)DIM*DIM];             // weights [k][n], half
__device__ __half g_wvh [(size_t)DIM*DIM];
__device__ __half g_woh [(size_t)DIM*DIM];

// ---------------------------------------------------------------------------
// helpers
// ---------------------------------------------------------------------------
__device__ __forceinline__ void mma_f16(float c[4],
    uint32_t a0, uint32_t a1, uint32_t a2, uint32_t a3,
    uint32_t b0, uint32_t b1)
{
    asm volatile(
        "mma.sync.aligned.m16n8k16.row.col.f32.f16.f16.f32 "
        "{%0,%1,%2,%3}, {%4,%5,%6,%7}, {%8,%9}, {%0,%1,%2,%3};\n"
        : "+f"(c[0]), "+f"(c[1]), "+f"(c[2]), "+f"(c[3])
        : "r"(a0), "r"(a1), "r"(a2), "r"(a3), "r"(b0), "r"(b1));
}

__device__ __forceinline__ void ldsm_x4(uint32_t r[4], uint32_t addr) {
    asm volatile("ldmatrix.sync.aligned.m8n8.x4.shared.b16 {%0,%1,%2,%3}, [%4];\n"
        : "=r"(r[0]), "=r"(r[1]), "=r"(r[2]), "=r"(r[3]) : "r"(addr));
}
__device__ __forceinline__ void ldsm_x4_t(uint32_t r[4], uint32_t addr) {
    asm volatile("ldmatrix.sync.aligned.m8n8.x4.trans.shared.b16 {%0,%1,%2,%3}, [%4];\n"
        : "=r"(r[0]), "=r"(r[1]), "=r"(r[2]), "=r"(r[3]) : "r"(addr));
}

__device__ __forceinline__ uint32_t smem_u32(const void* p) {
    return (uint32_t)__cvta_generic_to_shared(p);
}
__device__ __forceinline__ void cp16(uint32_t dst, const void* src) {
    asm volatile("cp.async.ca.shared.global [%0], [%1], 16;\n" :: "r"(dst), "l"(src));
}
__device__ __forceinline__ void cp_commit() {
    asm volatile("cp.async.commit_group;\n");
}
__device__ __forceinline__ void cp_wait2() {
    asm volatile("cp.async.wait_group 2;\n");
}

__device__ __forceinline__ uint32_t pack_h2(float a, float b) {
    __half2 h = __floats2half2_rn(a, b);
    return *reinterpret_cast<uint32_t*>(&h);
}

// ---------------------------------------------------------------------------
// prep: round x + 3 weights to fp16. Each thread: 8 floats -> 8 halfs (16B).
// ---------------------------------------------------------------------------
__global__ __launch_bounds__(256)
void prep_h(const float4* __restrict__ x, const float4* __restrict__ wk,
            const float4* __restrict__ wv, const float4* __restrict__ wo)
{
    const size_t X8 = (size_t)MROWS * DIM / 8;    // 1048576
    const size_t W8 = (size_t)DIM * DIM / 8;      // 131072
    size_t i = (size_t)blockIdx.x * 256 + threadIdx.x;
    const float4* src;
    uint4* dst;
    if (i < X8) {
        src = x + i * 2;
        dst = (uint4*)g_xh + i;
    } else {
        size_t j = i - X8;
        int seg = (int)(j / W8);
        size_t o = j % W8;
        src = (seg == 0 ? wk : (seg == 1 ? wv : wo)) + o * 2;
        dst = (uint4*)(seg == 0 ? g_wkh : (seg == 1 ? g_wvh : g_woh)) + o;
    }
    float4 a = src[0], b = src[1];
    uint4 u;
    u.x = pack_h2(a.x, a.y); u.y = pack_h2(a.z, a.w);
    u.z = pack_h2(b.x, b.y); u.w = pack_h2(b.z, b.w);
    *dst = u;
}

// ---------------------------------------------------------------------------
// Shared tiling constants. Block 64m x 128n, BK=32, 256 threads,
// warps 2(m) x 4(n), warp tile 32x32. 4-stage cp.async.
// ---------------------------------------------------------------------------
#define A_ROWB 80
#define B_ROWB 272
#define A_STGB (64*A_ROWB)             // 5120
#define B_STGB (32*B_ROWB)             // 8704
#define KV_BK_OFF (4*A_STGB)           // 20480
#define KV_BV_OFF (KV_BK_OFF + 4*B_STGB)  // 55296
#define KV_SMEM   (KV_BV_OFF + 4*B_STGB)  // 90112
#define OUT_B_OFF (4*A_STGB)
#define OUT_SMEM  (OUT_B_OFF + 4*B_STGB)  // 55296

// ---------------------------------------------------------------------------
// Fused K+V projection: k = x@Wk+bk, v = x@Wv+bv; epilogue writes
// g_ekh = exp(k), g_ekvh = exp(k)*v directly (no fp32 v round trip).
// ---------------------------------------------------------------------------
__global__ __launch_bounds__(256, 2)
void kv_h(const float* __restrict__ bkb, const float* __restrict__ bvb)
{
    extern __shared__ char smc[];
    const uint32_t sb = smem_u32(smc);

    const int tid  = threadIdx.x;
    const int lane = tid & 31;
    const int warp = tid >> 5;
    const int wm   = warp >> 2;        // 0..1
    const int wn   = warp & 3;         // 0..3
    const int r    = lane >> 2;
    const int cc   = lane & 3;

    const int bm = blockIdx.y << 6;
    const int bn = blockIdx.x << 7;

    // cp.async mappings
    const int arow = tid >> 2;               // 0..63
    const int ac8  = (tid & 3) << 3;
    const int br0  = tid >> 4;               // 0..15
    const int bc8  = (tid & 15) << 3;

    const __half* Abase = g_xh  + (size_t)bm * DIM;
    const __half* Kbase = g_wkh + bn;
    const __half* Vbase = g_wvh + bn;

    const uint32_t aAddr   = sb + arow * A_ROWB + ac8 * 2;
    const uint32_t bkAddr0 = sb + KV_BK_OFF + br0 * B_ROWB + bc8 * 2;
    const uint32_t bvAddr0 = sb + KV_BV_OFF + br0 * B_ROWB + bc8 * 2;

    auto issue = [&](int c) {
        const int st = c & 3;
        const int k0 = c << 5;
        cp16(aAddr + st * A_STGB, Abase + (size_t)arow * DIM + k0 + ac8);
        #pragma unroll
        for (int j = 0; j < 2; j++) {
            const int row = br0 + (j << 4);
            cp16(bkAddr0 + (j << 4) * B_ROWB + st * B_STGB,
                 Kbase + (size_t)(k0 + row) * DIM + bc8);
            cp16(bvAddr0 + (j << 4) * B_ROWB + st * B_STGB,
                 Vbase + (size_t)(k0 + row) * DIM + bc8);
        }
        cp_commit();
    };

    float acck[2][4][4] = {};
    float accv[2][4][4] = {};

    issue(0); issue(1); issue(2);

    const int lrow = lane & 15;
    const int lk8  = (lane >> 4) << 3;

    for (int c = 0; c < 32; c++) {
        const int st = c & 3;
        cp_wait2();
        __syncthreads();
        if (c + 3 < 32) issue(c + 3);
        else cp_commit();

        const uint32_t Abuf = sb + st * A_STGB;
        const uint32_t Kbuf = sb + KV_BK_OFF + st * B_STGB;
        const uint32_t Vbuf = sb + KV_BV_OFF + st * B_STGB;

        #pragma unroll
        for (int ks = 0; ks < 2; ks++) {
            const int k0h = ks << 4;
            uint32_t af[2][4], bfk[2][4], bfv[2][4];
            #pragma unroll
            for (int im = 0; im < 2; im++) {
                const int m0 = (wm << 5) + (im << 4);
                ldsm_x4(af[im], Abuf + (m0 + lrow) * A_ROWB + (k0h + lk8) * 2);
            }
            #pragma unroll
            for (int ng = 0; ng < 2; ng++) {
                const int n0 = (wn << 5) + (ng << 4);
                ldsm_x4_t(bfk[ng], Kbuf + (k0h + lrow) * B_ROWB + (n0 + lk8) * 2);
                ldsm_x4_t(bfv[ng], Vbuf + (k0h + lrow) * B_ROWB + (n0 + lk8) * 2);
            }
            #pragma unroll
            for (int im = 0; im < 2; im++)
                #pragma unroll
                for (int ng = 0; ng < 2; ng++) {
                    mma_f16(acck[im][2*ng],   af[im][0], af[im][1], af[im][2], af[im][3],
                            bfk[ng][0], bfk[ng][1]);
                    mma_f16(acck[im][2*ng+1], af[im][0], af[im][1], af[im][2], af[im][3],
                            bfk[ng][2], bfk[ng][3]);
                    mma_f16(accv[im][2*ng],   af[im][0], af[im][1], af[im][2], af[im][3],
                            bfv[ng][0], bfv[ng][1]);
                    mma_f16(accv[im][2*ng+1], af[im][0], af[im][1], af[im][2], af[im][3],
                            bfv[ng][2], bfv[ng][3]);
                }
        }
    }

    #pragma unroll
    for (int im = 0; im < 2; im++) {
        #pragma unroll
        for (int in = 0; in < 4; in++) {
            #pragma unroll
            for (int e = 0; e < 4; e++) {
                const int row = bm + (wm << 5) + (im << 4) + r + ((e >> 1) << 3);
                const int col = bn + (wn << 5) + (in << 3) + (cc << 1) + (e & 1);
                const float kv = acck[im][in][e] + bkb[col];
                const float vv = accv[im][in][e] + bvb[col];
                const float ek = __expf(kv);
                const int n = row >> 11, s = row & (SEQ - 1);
                const int h = col >> 7, d = col & 127;
                const size_t idx = (((size_t)(n * HEADS + h)) * SEQ + s) * HD + d;
                g_ekh[idx]  = __float2half_rn(ek);
                g_ekvh[idx] = __float2half_rn(ek * vv);
            }
        }
    }
}

// ---------------------------------------------------------------------------
// Output projection: out = aft @ Wo + bo.
// ---------------------------------------------------------------------------
__global__ __launch_bounds__(256, 2)
void out_h(const float* __restrict__ bias, float* __restrict__ out)
{
    extern __shared__ char smc[];
    const uint32_t sb = smem_u32(smc);

    const int tid  = threadIdx.x;
    const int lane = tid & 31;
    const int warp = tid >> 5;
    const int wm   = warp >> 2;
    const int wn   = warp & 3;
    const int r    = lane >> 2;
    const int cc   = lane & 3;

    const int bm = blockIdx.y << 6;
    const int bn = blockIdx.x << 7;

    const int arow = tid >> 2;
    const int ac8  = (tid & 3) << 3;
    const int br0  = tid >> 4;
    const int bc8  = (tid & 15) << 3;

    const __half* Abase = g_afth + (size_t)bm * DIM;
    const __half* Wbase = g_woh + bn;

    const uint32_t aAddr  = sb + arow * A_ROWB + ac8 * 2;
    const uint32_t bAddr0 = sb + OUT_B_OFF + br0 * B_ROWB + bc8 * 2;

    auto issue = [&](int c) {
        const int st = c & 3;
        const int k0 = c << 5;
        cp16(aAddr + st * A_STGB, Abase + (size_t)arow * DIM + k0 + ac8);
        #pragma unroll
        for (int j = 0; j < 2; j++) {
            const int row = br0 + (j << 4);
            cp16(bAddr0 + (j << 4) * B_ROWB + st * B_STGB,
                 Wbase + (size_t)(k0 + row) * DIM + bc8);
        }
        cp_commit();
    };

    float acc[2][4][4] = {};

    issue(0); issue(1); issue(2);

    const int lrow = lane & 15;
    const int lk8  = (lane >> 4) << 3;

    for (int c = 0; c < 32; c++) {
        const int st = c & 3;
        cp_wait2();
        __syncthreads();
        if (c + 3 < 32) issue(c + 3);
        else cp_commit();

        const uint32_t Abuf = sb + st * A_STGB;
        const uint32_t Bbuf = sb + OUT_B_OFF + st * B_STGB;

        #pragma unroll
        for (int ks = 0; ks < 2; ks++) {
            const int k0h = ks << 4;
            uint32_t af[2][4], bf[2][4];
            #pragma unroll
            for (int im = 0; im < 2; im++) {
                const int m0 = (wm << 5) + (im << 4);
                ldsm_x4(af[im], Abuf + (m0 + lrow) * A_ROWB + (k0h + lk8) * 2);
            }
            #pragma unroll
            for (int ng = 0; ng < 2; ng++) {
                const int n0 = (wn << 5) + (ng << 4);
                ldsm_x4_t(bf[ng], Bbuf + (k0h + lrow) * B_ROWB + (n0 + lk8) * 2);
            }
            #pragma unroll
            for (int im = 0; im < 2; im++)
                #pragma unroll
                for (int ng = 0; ng < 2; ng++) {
                    mma_f16(acc[im][2*ng],   af[im][0], af[im][1], af[im][2], af[im][3],
                            bf[ng][0], bf[ng][1]);
                    mma_f16(acc[im][2*ng+1], af[im][0], af[im][1], af[im][2], af[im][3],
                            bf[ng][2], bf[ng][3]);
                }
        }
    }

    #pragma unroll
    for (int im = 0; im < 2; im++) {
        #pragma unroll
        for (int in = 0; in < 4; in++) {
            #pragma unroll
            for (int e = 0; e < 4; e++) {
                const int row = bm + (wm << 5) + (im << 4) + r + ((e >> 1) << 3);
                const int col = bn + (wn << 5) + (in << 3) + (cc << 1) + (e & 1);
                out[(size_t)row * DIM + col] = acc[im][in][e] + bias[col];
            }
        }
    }
}

// ---------------------------------------------------------------------------
// AFT core: block 64t x 128d, 256 threads, warps 2(t)x4(d), warp tile 32x32.
// s-chunks of 32, causal, heavy-first. W tile [t][s] 80B rows (2 slots);
// ek/ekv [s][d] 272B rows (4 stages).
// ---------------------------------------------------------------------------
#define W_STGB  (64*A_ROWB)            // 5120
#define E_OFFB  (2*W_STGB)             // 10240
#define E_STGB  (32*B_ROWB)            // 8704
#define EV_OFFB (E_OFFB + 4*E_STGB)    // 45056
#define AFT_SMEM_B (EV_OFFB + 4*E_STGB)   // 79872

__global__ __launch_bounds__(256, 2)
void aft_h(const float* __restrict__ w_aft)
{
    extern __shared__ char smc[];
    const uint32_t sb = smem_u32(smc);

    const int tid  = threadIdx.x;
    const int lane = tid & 31;
    const int warp = tid >> 5;
    const int wm   = warp >> 2;        // 0..1 over t
    const int wn   = warp & 3;         // 0..3 over d
    const int r    = lane >> 2;
    const int cc   = lane & 3;

    const int bt = gridDim.x - 1 - blockIdx.x;   // heavy tiles first
    const int t0 = bt << 6;
    const int nh = blockIdx.y;
    const int n  = nh >> 3;
    const int h  = nh & 7;

    const float*  wbase  = w_aft  + ((size_t)h * SEQ + t0) * SEQ;
    const __half* ekbase = g_ekh  + (size_t)nh * SEQ * HD;
    const __half* evbase = g_ekvh + (size_t)nh * SEQ * HD;

    // w: 64x32 floats = 512 float4 per chunk; 2 per thread
    const int w_tl0 = tid >> 3;           // 0..31
    const int w_s4  = (tid & 7) << 2;
    // ek/ekv: 512 16B-chunks each; 2 per thread per matrix
    const int e_sl0 = tid >> 4;           // 0..15
    const int e_d8  = (tid & 15) << 3;

    const uint32_t ekAddr0 = sb + E_OFFB  + e_sl0 * B_ROWB + e_d8 * 2;
    const uint32_t evAddr0 = sb + EV_OFFB + e_sl0 * B_ROWB + e_d8 * 2;

    auto issueE = [&](int c) {
        const int st = c & 3;
        const int s0 = c << 5;
        #pragma unroll
        for (int j = 0; j < 2; j++) {
            const int row = e_sl0 + (j << 4);
            cp16(ekAddr0 + (j << 4) * B_ROWB + st * E_STGB,
                 ekbase + (size_t)(s0 + row) * HD + e_d8);
            cp16(evAddr0 + (j << 4) * B_ROWB + st * E_STGB,
                 evbase + (size_t)(s0 + row) * HD + e_d8);
        }
        cp_commit();
    };

    uint32_t wv2[2][2];
    auto loadW = [&](int s0) {
        #pragma unroll
        for (int j = 0; j < 2; j++) {
            const int tl = w_tl0 + (j << 5);
            float4 w4 = *(const float4*)(wbase + (size_t)tl * SEQ + s0 + w_s4);
            const int tg = t0 + tl;
            float e0 = (s0 + w_s4 + 0 <= tg) ? __expf(w4.x) : 0.f;
            float e1 = (s0 + w_s4 + 1 <= tg) ? __expf(w4.y) : 0.f;
            float e2 = (s0 + w_s4 + 2 <= tg) ? __expf(w4.z) : 0.f;
            float e3 = (s0 + w_s4 + 3 <= tg) ? __expf(w4.w) : 0.f;
            wv2[j][0] = pack_h2(e0, e1);
            wv2[j][1] = pack_h2(e2, e3);
        }
    };
    auto storeW = [&](int slot) {
        #pragma unroll
        for (int j = 0; j < 2; j++) {
            const int tl = w_tl0 + (j << 5);
            *(uint2*)(smc + slot * W_STGB + tl * A_ROWB + w_s4 * 2) =
                make_uint2(wv2[j][0], wv2[j][1]);
        }
    };

    float accN[2][4][4] = {};
    float accD[2][4][4] = {};

    const int nch = (bt + 1) << 1;    // s-chunks of 32 through diagonal
    loadW(0);
    issueE(0); issueE(1); issueE(2);

    const int lrow = lane & 15;
    const int lk8  = (lane >> 4) << 3;

    for (int c = 0; c < nch; c++) {
        const int wslot = c & 1;
        const int ebuf  = c & 3;
        storeW(wslot);
        cp_wait2();
        __syncthreads();
        if (c + 3 < nch) issueE(c + 3);
        else cp_commit();
        if (c + 1 < nch) loadW((c + 1) << 5);

        const uint32_t Wbuf = sb + wslot * W_STGB;
        const uint32_t Kbuf = sb + E_OFFB  + ebuf * E_STGB;
        const uint32_t Vbuf = sb + EV_OFFB + ebuf * E_STGB;

        #pragma unroll
        for (int ks = 0; ks < 2; ks++) {
            const int k0h = ks << 4;
            uint32_t af[2][4], bk[2][4], bv[2][4];
            #pragma unroll
            for (int im = 0; im < 2; im++) {
                const int m0 = (wm << 5) + (im << 4);
                ldsm_x4(af[im], Wbuf + (m0 + lrow) * A_ROWB + (k0h + lk8) * 2);
            }
            #pragma unroll
            for (int ng = 0; ng < 2; ng++) {
                const int n0 = (wn << 5) + (ng << 4);
                ldsm_x4_t(bk[ng], Kbuf + (k0h + lrow) * B_ROWB + (n0 + lk8) * 2);
                ldsm_x4_t(bv[ng], Vbuf + (k0h + lrow) * B_ROWB + (n0 + lk8) * 2);
            }
            #pragma unroll
            for (int im = 0; im < 2; im++)
                #pragma unroll
                for (int ng = 0; ng < 2; ng++) {
                    mma_f16(accN[im][2*ng],   af[im][0], af[im][1], af[im][2], af[im][3],
                            bv[ng][0], bv[ng][1]);
                    mma_f16(accN[im][2*ng+1], af[im][0], af[im][1], af[im][2], af[im][3],
                            bv[ng][2], bv[ng][3]);
                    mma_f16(accD[im][2*ng],   af[im][0], af[im][1], af[im][2], af[im][3],
                            bk[ng][0], bk[ng][1]);
                    mma_f16(accD[im][2*ng+1], af[im][0], af[im][1], af[im][2], af[im][3],
                            bk[ng][2], bk[ng][3]);
                }
        }
        __syncthreads();
    }

    #pragma unroll
    for (int im = 0; im < 2; im++) {
        #pragma unroll
        for (int in = 0; in < 4; in++) {
            #pragma unroll
            for (int e = 0; e < 4; e++) {
                const int t = t0 + (wm << 5) + (im << 4) + r + ((e >> 1) << 3);
                const int d = (wn << 5) + (in << 3) + (cc << 1) + (e & 1);
                g_afth[((size_t)(n * SEQ + t)) * DIM + h * HD + d] =
                    __float2half_rn(accN[im][in][e] / accD[im][in][e]);
            }
        }
    }
}

extern "C" void kernel_launch(void* const* d_in, const int* in_sizes, int n_in,
                              void* d_out, int out_size)
{
    const float* x     = (const float*)d_in[0];
    const float* Wk    = (const float*)d_in[1];
    const float* bk    = (const float*)d_in[2];
    const float* Wv    = (const float*)d_in[3];
    const float* bv    = (const float*)d_in[4];
    const float* w_aft = (const float*)d_in[5];
    const float* Wo    = (const float*)d_in[6];
    const float* bo    = (const float*)d_in[7];
    float* out = (float*)d_out;

    cudaFuncSetAttribute(kv_h,  cudaFuncAttributeMaxDynamicSharedMemorySize, KV_SMEM);
    cudaFuncSetAttribute(out_h, cudaFuncAttributeMaxDynamicSharedMemorySize, OUT_SMEM);
    cudaFuncSetAttribute(aft_h, cudaFuncAttributeMaxDynamicSharedMemorySize, AFT_SMEM_B);

    prep_h<<<5632, 256>>>((const float4*)x, (const float4*)Wk,
                          (const float4*)Wv, (const float4*)Wo);

    kv_h <<<dim3(DIM / 128, MROWS / 64), 256, KV_SMEM>>>(bk, bv);
    aft_h<<<dim3(SEQ / 64, NB * HEADS), 256, AFT_SMEM_B>>>(w_aft);
    out_h<<<dim3(DIM / 128, MROWS / 64), 256, OUT_SMEM>>>(bo, out);
}

// round 11
// speedup vs baseline: 2.3280x; 1.0765x over previous
#include <cuda_runtime.h>
#include <cuda_fp16.h>
#include <cstdint>

#define NB    4
#define SEQ   2048
#define DIM   1024
#define HEADS 8
#define HD    128
#define MROWS (NB*SEQ)

// Scratch (device globals — no allocation allowed)
__device__ __half g_ekh [(size_t)NB*HEADS*SEQ*HD];     // exp(k), half
__device__ __half g_ekvh[(size_t)NB*HEADS*SEQ*HD];     // exp(k)*v, half
__device__ __half g_afth[(size_t)MROWS*DIM];           // AFT output, half
__device__ __half g_xh  [(size_t)MROWS*DIM];           // x, half
__device__ __half g_wkh [(size_t)DIM*DIM];             // weights [k][n], half
__device__ __half g_wvh [(size_t)DIM*DIM];
__device__ __half g_woh [(size_t)DIM*DIM];
__device__ __half g_ewh [(size_t)HEADS*SEQ*SEQ];       // exp(w_aft), causal-masked, half

// ---------------------------------------------------------------------------
// helpers
// ---------------------------------------------------------------------------
__device__ __forceinline__ void mma_f16(float c[4],
    uint32_t a0, uint32_t a1, uint32_t a2, uint32_t a3,
    uint32_t b0, uint32_t b1)
{
    asm volatile(
        "mma.sync.aligned.m16n8k16.row.col.f32.f16.f16.f32 "
        "{%0,%1,%2,%3}, {%4,%5,%6,%7}, {%8,%9}, {%0,%1,%2,%3};\n"
        : "+f"(c[0]), "+f"(c[1]), "+f"(c[2]), "+f"(c[3])
        : "r"(a0), "r"(a1), "r"(a2), "r"(a3), "r"(b0), "r"(b1));
}

__device__ __forceinline__ void ldsm_x4(uint32_t r[4], uint32_t addr) {
    asm volatile("ldmatrix.sync.aligned.m8n8.x4.shared.b16 {%0,%1,%2,%3}, [%4];\n"
        : "=r"(r[0]), "=r"(r[1]), "=r"(r[2]), "=r"(r[3]) : "r"(addr));
}
__device__ __forceinline__ void ldsm_x4_t(uint32_t r[4], uint32_t addr) {
    asm volatile("ldmatrix.sync.aligned.m8n8.x4.trans.shared.b16 {%0,%1,%2,%3}, [%4];\n"
        : "=r"(r[0]), "=r"(r[1]), "=r"(r[2]), "=r"(r[3]) : "r"(addr));
}

__device__ __forceinline__ uint32_t smem_u32(const void* p) {
    return (uint32_t)__cvta_generic_to_shared(p);
}
__device__ __forceinline__ void cp16(uint32_t dst, const void* src) {
    asm volatile("cp.async.ca.shared.global [%0], [%1], 16;\n" :: "r"(dst), "l"(src));
}
__device__ __forceinline__ void cp_commit() {
    asm volatile("cp.async.commit_group;\n");
}
__device__ __forceinline__ void cp_wait2() {
    asm volatile("cp.async.wait_group 2;\n");
}

__device__ __forceinline__ uint32_t pack_h2(float a, float b) {
    __half2 h = __floats2half2_rn(a, b);
    return *reinterpret_cast<uint32_t*>(&h);
}

// ---------------------------------------------------------------------------
// prep_h: round x + 3 weights to fp16.
// ---------------------------------------------------------------------------
__global__ __launch_bounds__(256)
void prep_h(const float4* __restrict__ x, const float4* __restrict__ wk,
            const float4* __restrict__ wv, const float4* __restrict__ wo)
{
    const size_t X8 = (size_t)MROWS * DIM / 8;    // 1048576
    const size_t W8 = (size_t)DIM * DIM / 8;      // 131072
    size_t i = (size_t)blockIdx.x * 256 + threadIdx.x;
    const float4* src;
    uint4* dst;
    if (i < X8) {
        src = x + i * 2;
        dst = (uint4*)g_xh + i;
    } else {
        size_t j = i - X8;
        int seg = (int)(j / W8);
        size_t o = j % W8;
        src = (seg == 0 ? wk : (seg == 1 ? wv : wo)) + o * 2;
        dst = (uint4*)(seg == 0 ? g_wkh : (seg == 1 ? g_wvh : g_woh)) + o;
    }
    float4 a = src[0], b = src[1];
    uint4 u;
    u.x = pack_h2(a.x, a.y); u.y = pack_h2(a.z, a.w);
    u.z = pack_h2(b.x, b.y); u.w = pack_h2(b.z, b.w);
    *dst = u;
}

// ---------------------------------------------------------------------------
// prep_ew: ewh[h][t][s] = (s<=t) ? half(exp(w_aft[h][t][s])) : 0.
// 8 elements per thread (one row-aligned group of 8).
// ---------------------------------------------------------------------------
__global__ __launch_bounds__(256)
void prep_ew(const float4* __restrict__ w_aft)
{
    size_t i = (size_t)blockIdx.x * 256 + threadIdx.x;   // 8-half groups
    const size_t base = i * 8;
    const int s0 = (int)(base & (SEQ - 1));
    const int t  = (int)((base >> 11) & (SEQ - 1));
    float4 a = w_aft[i * 2], b = w_aft[i * 2 + 1];
    float e[8];
    e[0] = (s0 + 0 <= t) ? __expf(a.x) : 0.f;
    e[1] = (s0 + 1 <= t) ? __expf(a.y) : 0.f;
    e[2] = (s0 + 2 <= t) ? __expf(a.z) : 0.f;
    e[3] = (s0 + 3 <= t) ? __expf(a.w) : 0.f;
    e[4] = (s0 + 4 <= t) ? __expf(b.x) : 0.f;
    e[5] = (s0 + 5 <= t) ? __expf(b.y) : 0.f;
    e[6] = (s0 + 6 <= t) ? __expf(b.z) : 0.f;
    e[7] = (s0 + 7 <= t) ? __expf(b.w) : 0.f;
    uint4 u;
    u.x = pack_h2(e[0], e[1]); u.y = pack_h2(e[2], e[3]);
    u.z = pack_h2(e[4], e[5]); u.w = pack_h2(e[6], e[7]);
    ((uint4*)g_ewh)[i] = u;
}

// ---------------------------------------------------------------------------
// Tiling constants
// ---------------------------------------------------------------------------
#define A_ROWB 80
#define B_ROWB 272
#define A_STGB (64*A_ROWB)             // 5120
#define B_STGB (32*B_ROWB)             // 8704

// kv: block 64m x 128n, warps 2(m)x4(n), warp tile 32x32 (dual acc)
#define KV_BK_OFF (4*A_STGB)              // 20480
#define KV_BV_OFF (KV_BK_OFF + 4*B_STGB)  // 55296
#define KV_SMEM   (KV_BV_OFF + 4*B_STGB)  // 90112

// out: block 64m x 256n, warps 2(m)x4(n), warp tile 32x64
#define O_ROWB 528
#define O_STGB (32*O_ROWB)             // 16896
#define OUT_B_OFF (4*A_STGB)           // 20480
#define OUT_SMEM  (OUT_B_OFF + 4*O_STGB)  // 88064

// aft: block 64t x 128d, warps 2(t)x4(d), warp tile 32x32 (dual acc)
#define AW_OFF  0
#define AE_OFF  (4*A_STGB)             // 20480
#define AV_OFF  (AE_OFF + 4*B_STGB)    // 55296
#define AFT_SMEM (AV_OFF + 4*B_STGB)   // 90112

// ---------------------------------------------------------------------------
// Fused K+V projection
// ---------------------------------------------------------------------------
__global__ __launch_bounds__(256, 2)
void kv_h(const float* __restrict__ bkb, const float* __restrict__ bvb)
{
    extern __shared__ char smc[];
    const uint32_t sb = smem_u32(smc);

    const int tid  = threadIdx.x;
    const int lane = tid & 31;
    const int warp = tid >> 5;
    const int wm   = warp >> 2;
    const int wn   = warp & 3;
    const int r    = lane >> 2;
    const int cc   = lane & 3;

    const int bm = blockIdx.y << 6;
    const int bn = blockIdx.x << 7;

    const int arow = tid >> 2;
    const int ac8  = (tid & 3) << 3;
    const int br0  = tid >> 4;
    const int bc8  = (tid & 15) << 3;

    const __half* Abase = g_xh  + (size_t)bm * DIM;
    const __half* Kbase = g_wkh + bn;
    const __half* Vbase = g_wvh + bn;

    const uint32_t aAddr   = sb + arow * A_ROWB + ac8 * 2;
    const uint32_t bkAddr0 = sb + KV_BK_OFF + br0 * B_ROWB + bc8 * 2;
    const uint32_t bvAddr0 = sb + KV_BV_OFF + br0 * B_ROWB + bc8 * 2;

    auto issue = [&](int c) {
        const int st = c & 3;
        const int k0 = c << 5;
        cp16(aAddr + st * A_STGB, Abase + (size_t)arow * DIM + k0 + ac8);
        #pragma unroll
        for (int j = 0; j < 2; j++) {
            const int row = br0 + (j << 4);
            cp16(bkAddr0 + (j << 4) * B_ROWB + st * B_STGB,
                 Kbase + (size_t)(k0 + row) * DIM + bc8);
            cp16(bvAddr0 + (j << 4) * B_ROWB + st * B_STGB,
                 Vbase + (size_t)(k0 + row) * DIM + bc8);
        }
        cp_commit();
    };

    float acck[2][4][4] = {};
    float accv[2][4][4] = {};

    issue(0); issue(1); issue(2);

    const int lrow = lane & 15;
    const int lk8  = (lane >> 4) << 3;

    for (int c = 0; c < 32; c++) {
        const int st = c & 3;
        cp_wait2();
        __syncthreads();
        if (c + 3 < 32) issue(c + 3);
        else cp_commit();

        const uint32_t Abuf = sb + st * A_STGB;
        const uint32_t Kbuf = sb + KV_BK_OFF + st * B_STGB;
        const uint32_t Vbuf = sb + KV_BV_OFF + st * B_STGB;

        #pragma unroll
        for (int ks = 0; ks < 2; ks++) {
            const int k0h = ks << 4;
            uint32_t af[2][4], bfk[2][4], bfv[2][4];
            #pragma unroll
            for (int im = 0; im < 2; im++) {
                const int m0 = (wm << 5) + (im << 4);
                ldsm_x4(af[im], Abuf + (m0 + lrow) * A_ROWB + (k0h + lk8) * 2);
            }
            #pragma unroll
            for (int ng = 0; ng < 2; ng++) {
                const int n0 = (wn << 5) + (ng << 4);
                ldsm_x4_t(bfk[ng], Kbuf + (k0h + lrow) * B_ROWB + (n0 + lk8) * 2);
                ldsm_x4_t(bfv[ng], Vbuf + (k0h + lrow) * B_ROWB + (n0 + lk8) * 2);
            }
            #pragma unroll
            for (int im = 0; im < 2; im++)
                #pragma unroll
                for (int ng = 0; ng < 2; ng++) {
                    mma_f16(acck[im][2*ng],   af[im][0], af[im][1], af[im][2], af[im][3],
                            bfk[ng][0], bfk[ng][1]);
                    mma_f16(acck[im][2*ng+1], af[im][0], af[im][1], af[im][2], af[im][3],
                            bfk[ng][2], bfk[ng][3]);
                    mma_f16(accv[im][2*ng],   af[im][0], af[im][1], af[im][2], af[im][3],
                            bfv[ng][0], bfv[ng][1]);
                    mma_f16(accv[im][2*ng+1], af[im][0], af[im][1], af[im][2], af[im][3],
                            bfv[ng][2], bfv[ng][3]);
                }
        }
    }

    #pragma unroll
    for (int im = 0; im < 2; im++) {
        #pragma unroll
        for (int in = 0; in < 4; in++) {
            #pragma unroll
            for (int e = 0; e < 4; e++) {
                const int row = bm + (wm << 5) + (im << 4) + r + ((e >> 1) << 3);
                const int col = bn + (wn << 5) + (in << 3) + (cc << 1) + (e & 1);
                const float kv = acck[im][in][e] + bkb[col];
                const float vv = accv[im][in][e] + bvb[col];
                const float ek = __expf(kv);
                const int n = row >> 11, s = row & (SEQ - 1);
                const int h = col >> 7, d = col & 127;
                const size_t idx = (((size_t)(n * HEADS + h)) * SEQ + s) * HD + d;
                g_ekh[idx]  = __float2half_rn(ek);
                g_ekvh[idx] = __float2half_rn(ek * vv);
            }
        }
    }
}

// ---------------------------------------------------------------------------
// Output projection: block 64m x 256n, warp tile 32x64.
// ---------------------------------------------------------------------------
__global__ __launch_bounds__(256, 2)
void out_h(const float* __restrict__ bias, float* __restrict__ out)
{
    extern __shared__ char smc[];
    const uint32_t sb = smem_u32(smc);

    const int tid  = threadIdx.x;
    const int lane = tid & 31;
    const int warp = tid >> 5;
    const int wm   = warp >> 2;
    const int wn   = warp & 3;
    const int r    = lane >> 2;
    const int cc   = lane & 3;

    const int bm = blockIdx.y << 6;
    const int bn = blockIdx.x << 8;

    const int arow = tid >> 2;
    const int ac8  = (tid & 3) << 3;
    const int br0  = tid >> 5;           // 0..7
    const int bc8  = (tid & 31) << 3;    // 0..248

    const __half* Abase = g_afth + (size_t)bm * DIM;
    const __half* Wbase = g_woh + bn;

    const uint32_t aAddr  = sb + arow * A_ROWB + ac8 * 2;
    const uint32_t bAddr0 = sb + OUT_B_OFF + br0 * O_ROWB + bc8 * 2;

    auto issue = [&](int c) {
        const int st = c & 3;
        const int k0 = c << 5;
        cp16(aAddr + st * A_STGB, Abase + (size_t)arow * DIM + k0 + ac8);
        #pragma unroll
        for (int j = 0; j < 4; j++) {
            const int row = br0 + (j << 3);
            cp16(bAddr0 + (j << 3) * O_ROWB + st * O_STGB,
                 Wbase + (size_t)(k0 + row) * DIM + bc8);
        }
        cp_commit();
    };

    float acc[2][8][4] = {};

    issue(0); issue(1); issue(2);

    const int lrow = lane & 15;
    const int lk8  = (lane >> 4) << 3;

    for (int c = 0; c < 32; c++) {
        const int st = c & 3;
        cp_wait2();
        __syncthreads();
        if (c + 3 < 32) issue(c + 3);
        else cp_commit();

        const uint32_t Abuf = sb + st * A_STGB;
        const uint32_t Bbuf = sb + OUT_B_OFF + st * O_STGB;

        #pragma unroll
        for (int ks = 0; ks < 2; ks++) {
            const int k0h = ks << 4;
            uint32_t af[2][4], bf[4][4];
            #pragma unroll
            for (int im = 0; im < 2; im++) {
                const int m0 = (wm << 5) + (im << 4);
                ldsm_x4(af[im], Abuf + (m0 + lrow) * A_ROWB + (k0h + lk8) * 2);
            }
            #pragma unroll
            for (int ng = 0; ng < 4; ng++) {
                const int n0 = (wn << 6) + (ng << 4);
                ldsm_x4_t(bf[ng], Bbuf + (k0h + lrow) * O_ROWB + (n0 + lk8) * 2);
            }
            #pragma unroll
            for (int im = 0; im < 2; im++)
                #pragma unroll
                for (int ng = 0; ng < 4; ng++) {
                    mma_f16(acc[im][2*ng],   af[im][0], af[im][1], af[im][2], af[im][3],
                            bf[ng][0], bf[ng][1]);
                    mma_f16(acc[im][2*ng+1], af[im][0], af[im][1], af[im][2], af[im][3],
                            bf[ng][2], bf[ng][3]);
                }
        }
    }

    #pragma unroll
    for (int im = 0; im < 2; im++) {
        #pragma unroll
        for (int in = 0; in < 8; in++) {
            #pragma unroll
            for (int e = 0; e < 4; e++) {
                const int row = bm + (wm << 5) + (im << 4) + r + ((e >> 1) << 3);
                const int col = bn + (wn << 6) + (in << 3) + (cc << 1) + (e & 1);
                out[(size_t)row * DIM + col] = acc[im][in][e] + bias[col];
            }
        }
    }
}

// ---------------------------------------------------------------------------
// AFT core: block 64t x 128d, warps 2(t)x4(d), warp tile 32x32 dual-acc.
// All three operands (ew, ek, ekv) via 4-stage cp.async; no exp in-loop.
// ---------------------------------------------------------------------------
__global__ __launch_bounds__(256, 2)
void aft_h(int dummy)
{
    extern __shared__ char smc[];
    const uint32_t sb = smem_u32(smc);

    const int tid  = threadIdx.x;
    const int lane = tid & 31;
    const int warp = tid >> 5;
    const int wm   = warp >> 2;
    const int wn   = warp & 3;
    const int r    = lane >> 2;
    const int cc   = lane & 3;

    const int bt = gridDim.x - 1 - blockIdx.x;   // heavy tiles first
    const int t0 = bt << 6;
    const int nh = blockIdx.y;
    const int n  = nh >> 3;
    const int h  = nh & 7;

    const __half* wbase  = g_ewh  + ((size_t)h * SEQ + t0) * SEQ;
    const __half* ekbase = g_ekh  + (size_t)nh * SEQ * HD;
    const __half* evbase = g_ekvh + (size_t)nh * SEQ * HD;

    // W: 64 rows x 32 halfs (64B) per chunk = 256 cp16; 1 per thread
    const int w_tl  = tid >> 2;           // 0..63
    const int w_c8  = (tid & 3) << 3;     // half offset 0,8,16,24
    // ek/ekv: 512 cp16 each; 2 per thread
    const int e_sl0 = tid >> 4;           // 0..15
    const int e_d8  = (tid & 15) << 3;

    const uint32_t wAddr   = sb + AW_OFF + w_tl * A_ROWB + w_c8 * 2;
    const uint32_t ekAddr0 = sb + AE_OFF + e_sl0 * B_ROWB + e_d8 * 2;
    const uint32_t evAddr0 = sb + AV_OFF + e_sl0 * B_ROWB + e_d8 * 2;

    auto issue = [&](int c) {
        const int st = c & 3;
        const int s0 = c << 5;
        cp16(wAddr + st * A_STGB, wbase + (size_t)w_tl * SEQ + s0 + w_c8);
        #pragma unroll
        for (int j = 0; j < 2; j++) {
            const int row = e_sl0 + (j << 4);
            cp16(ekAddr0 + (j << 4) * B_ROWB + st * B_STGB,
                 ekbase + (size_t)(s0 + row) * HD + e_d8);
            cp16(evAddr0 + (j << 4) * B_ROWB + st * B_STGB,
                 evbase + (size_t)(s0 + row) * HD + e_d8);
        }
        cp_commit();
    };

    float accN[2][4][4] = {};
    float accD[2][4][4] = {};

    const int nch = (bt + 1) << 1;    // s-chunks of 32 through diagonal
    issue(0); issue(1); issue(2);

    const int lrow = lane & 15;
    const int lk8  = (lane >> 4) << 3;

    for (int c = 0; c < nch; c++) {
        const int st = c & 3;
        cp_wait2();
        __syncthreads();
        if (c + 3 < nch) issue(c + 3);
        else cp_commit();

        const uint32_t Wbuf = sb + AW_OFF + st * A_STGB;
        const uint32_t Kbuf = sb + AE_OFF + st * B_STGB;
        const uint32_t Vbuf = sb + AV_OFF + st * B_STGB;

        #pragma unroll
        for (int ks = 0; ks < 2; ks++) {
            const int k0h = ks << 4;
            uint32_t af[2][4], bk[2][4], bv[2][4];
            #pragma unroll
            for (int im = 0; im < 2; im++) {
                const int m0 = (wm << 5) + (im << 4);
                ldsm_x4(af[im], Wbuf + (m0 + lrow) * A_ROWB + (k0h + lk8) * 2);
            }
            #pragma unroll
            for (int ng = 0; ng < 2; ng++) {
                const int n0 = (wn << 5) + (ng << 4);
                ldsm_x4_t(bk[ng], Kbuf + (k0h + lrow) * B_ROWB + (n0 + lk8) * 2);
                ldsm_x4_t(bv[ng], Vbuf + (k0h + lrow) * B_ROWB + (n0 + lk8) * 2);
            }
            #pragma unroll
            for (int im = 0; im < 2; im++)
                #pragma unroll
                for (int ng = 0; ng < 2; ng++) {
                    mma_f16(accN[im][2*ng],   af[im][0], af[im][1], af[im][2], af[im][3],
                            bv[ng][0], bv[ng][1]);
                    mma_f16(accN[im][2*ng+1], af[im][0], af[im][1], af[im][2], af[im][3],
                            bv[ng][2], bv[ng][3]);
                    mma_f16(accD[im][2*ng],   af[im][0], af[im][1], af[im][2], af[im][3],
                            bk[ng][0], bk[ng][1]);
                    mma_f16(accD[im][2*ng+1], af[im][0], af[im][1], af[im][2], af[im][3],
                            bk[ng][2], bk[ng][3]);
                }
        }
    }

    #pragma unroll
    for (int im = 0; im < 2; im++) {
        #pragma unroll
        for (int in = 0; in < 4; in++) {
            #pragma unroll
            for (int e = 0; e < 4; e++) {
                const int t = t0 + (wm << 5) + (im << 4) + r + ((e >> 1) << 3);
                const int d = (wn << 5) + (in << 3) + (cc << 1) + (e & 1);
                g_afth[((size_t)(n * SEQ + t)) * DIM + h * HD + d] =
                    __float2half_rn(accN[im][in][e] / accD[im][in][e]);
            }
        }
    }
}

extern "C" void kernel_launch(void* const* d_in, const int* in_sizes, int n_in,
                              void* d_out, int out_size)
{
    const float* x     = (const float*)d_in[0];
    const float* Wk    = (const float*)d_in[1];
    const float* bk    = (const float*)d_in[2];
    const float* Wv    = (const float*)d_in[3];
    const float* bv    = (const float*)d_in[4];
    const float* w_aft = (const float*)d_in[5];
    const float* Wo    = (const float*)d_in[6];
    const float* bo    = (const float*)d_in[7];
    float* out = (float*)d_out;

    cudaFuncSetAttribute(kv_h,  cudaFuncAttributeMaxDynamicSharedMemorySize, KV_SMEM);
    cudaFuncSetAttribute(out_h, cudaFuncAttributeMaxDynamicSharedMemorySize, OUT_SMEM);
    cudaFuncSetAttribute(aft_h, cudaFuncAttributeMaxDynamicSharedMemorySize, AFT_SMEM);

    prep_h <<<5632, 256>>>((const float4*)x, (const float4*)Wk,
                           (const float4*)Wv, (const float4*)Wo);
    prep_ew<<<(size_t)HEADS*SEQ*SEQ/8/256, 256>>>((const float4*)w_aft);

    kv_h <<<dim3(DIM / 128, MROWS / 64), 256, KV_SMEM>>>(bk, bv);
    aft_h<<<dim3(SEQ / 64, NB * HEADS), 256, AFT_SMEM>>>(0);
    out_h<<<dim3(DIM / 256, MROWS / 64), 256, OUT_SMEM>>>(bo, out);
}

// round 12
// speedup vs baseline: 2.3920x; 1.0275x over previous
#include <cuda_runtime.h>
#include <cuda_fp16.h>
#include <cstdint>

#define NB    4
#define SEQ   2048
#define DIM   1024
#define HEADS 8
#define HD    128
#define MROWS (NB*SEQ)

// Scratch (device globals — no allocation allowed)
__device__ __half g_ekh [(size_t)NB*HEADS*SEQ*HD];     // exp(k), half
__device__ __half g_ekvh[(size_t)NB*HEADS*SEQ*HD];     // exp(k)*v, half
__device__ __half g_afth[(size_t)MROWS*DIM];           // AFT output, half
__device__ __half g_xh  [(size_t)MROWS*DIM];           // x, half
__device__ __half g_wkh [(size_t)DIM*DIM];             // weights [k][n], half
__device__ __half g_wvh [(size_t)DIM*DIM];
__device__ __half g_woh [(size_t)DIM*DIM];
__device__ __half g_ewh [(size_t)HEADS*SEQ*SEQ];       // exp(w_aft), causal-masked, half

// ---------------------------------------------------------------------------
// helpers
// ---------------------------------------------------------------------------
__device__ __forceinline__ void mma_f16(float c[4],
    uint32_t a0, uint32_t a1, uint32_t a2, uint32_t a3,
    uint32_t b0, uint32_t b1)
{
    asm volatile(
        "mma.sync.aligned.m16n8k16.row.col.f32.f16.f16.f32 "
        "{%0,%1,%2,%3}, {%4,%5,%6,%7}, {%8,%9}, {%0,%1,%2,%3};\n"
        : "+f"(c[0]), "+f"(c[1]), "+f"(c[2]), "+f"(c[3])
        : "r"(a0), "r"(a1), "r"(a2), "r"(a3), "r"(b0), "r"(b1));
}

__device__ __forceinline__ void ldsm_x4(uint32_t r[4], uint32_t addr) {
    asm volatile("ldmatrix.sync.aligned.m8n8.x4.shared.b16 {%0,%1,%2,%3}, [%4];\n"
        : "=r"(r[0]), "=r"(r[1]), "=r"(r[2]), "=r"(r[3]) : "r"(addr));
}
__device__ __forceinline__ void ldsm_x4_t(uint32_t r[4], uint32_t addr) {
    asm volatile("ldmatrix.sync.aligned.m8n8.x4.trans.shared.b16 {%0,%1,%2,%3}, [%4];\n"
        : "=r"(r[0]), "=r"(r[1]), "=r"(r[2]), "=r"(r[3]) : "r"(addr));
}

__device__ __forceinline__ uint32_t smem_u32(const void* p) {
    return (uint32_t)__cvta_generic_to_shared(p);
}
// .cg: bypass L1 — all tiles are streamed exactly once, keep L1 port for ldsm
__device__ __forceinline__ void cp16(uint32_t dst, const void* src) {
    asm volatile("cp.async.cg.shared.global [%0], [%1], 16;\n" :: "r"(dst), "l"(src));
}
__device__ __forceinline__ void cp_commit() {
    asm volatile("cp.async.commit_group;\n");
}
__device__ __forceinline__ void cp_wait2() {
    asm volatile("cp.async.wait_group 2;\n");
}

__device__ __forceinline__ uint32_t pack_h2(float a, float b) {
    __half2 h = __floats2half2_rn(a, b);
    return *reinterpret_cast<uint32_t*>(&h);
}

// ---------------------------------------------------------------------------
// prep: one kernel — rounds x + 3 weights to fp16 AND builds the causal
// exp(w_aft) fp16 table. Each thread handles one group of 8 floats.
// ---------------------------------------------------------------------------
#define X8  ((size_t)MROWS*DIM/8)             // 1048576
#define W8  ((size_t)DIM*DIM/8)               // 131072
#define EW8 ((size_t)HEADS*SEQ*SEQ/8)         // 4194304
#define PREP_GROUPS (X8 + 3*W8 + EW8)         // 5636096
#define PREP_BLOCKS (PREP_GROUPS/256)         // 22016

__global__ __launch_bounds__(256)
void prep_all(const float4* __restrict__ x, const float4* __restrict__ wk,
              const float4* __restrict__ wv, const float4* __restrict__ wo,
              const float4* __restrict__ w_aft)
{
    size_t i = (size_t)blockIdx.x * 256 + threadIdx.x;
    if (i < X8 + 3*W8) {
        const float4* src;
        uint4* dst;
        if (i < X8) {
            src = x + i * 2;
            dst = (uint4*)g_xh + i;
        } else {
            size_t j = i - X8;
            int seg = (int)(j / W8);
            size_t o = j % W8;
            src = (seg == 0 ? wk : (seg == 1 ? wv : wo)) + o * 2;
            dst = (uint4*)(seg == 0 ? g_wkh : (seg == 1 ? g_wvh : g_woh)) + o;
        }
        float4 a = src[0], b = src[1];
        uint4 u;
        u.x = pack_h2(a.x, a.y); u.y = pack_h2(a.z, a.w);
        u.z = pack_h2(b.x, b.y); u.w = pack_h2(b.z, b.w);
        *dst = u;
    } else {
        size_t j = i - X8 - 3*W8;                  // ew group index
        const size_t base = j * 8;
        const int s0 = (int)(base & (SEQ - 1));
        const int t  = (int)((base >> 11) & (SEQ - 1));
        float4 a = w_aft[j * 2], b = w_aft[j * 2 + 1];
        float e[8];
        e[0] = (s0 + 0 <= t) ? __expf(a.x) : 0.f;
        e[1] = (s0 + 1 <= t) ? __expf(a.y) : 0.f;
        e[2] = (s0 + 2 <= t) ? __expf(a.z) : 0.f;
        e[3] = (s0 + 3 <= t) ? __expf(a.w) : 0.f;
        e[4] = (s0 + 4 <= t) ? __expf(b.x) : 0.f;
        e[5] = (s0 + 5 <= t) ? __expf(b.y) : 0.f;
        e[6] = (s0 + 6 <= t) ? __expf(b.z) : 0.f;
        e[7] = (s0 + 7 <= t) ? __expf(b.w) : 0.f;
        uint4 u;
        u.x = pack_h2(e[0], e[1]); u.y = pack_h2(e[2], e[3]);
        u.z = pack_h2(e[4], e[5]); u.w = pack_h2(e[6], e[7]);
        ((uint4*)g_ewh)[j] = u;
    }
}

// ---------------------------------------------------------------------------
// Tiling constants
// ---------------------------------------------------------------------------
#define A_ROWB 80
#define B_ROWB 272
#define A_STGB (64*A_ROWB)             // 5120
#define B_STGB (32*B_ROWB)             // 8704

// kv: block 64m x 128n, warps 2(m)x4(n), warp tile 32x32 (dual acc)
#define KV_BK_OFF (4*A_STGB)              // 20480
#define KV_BV_OFF (KV_BK_OFF + 4*B_STGB)  // 55296
#define KV_SMEM   (KV_BV_OFF + 4*B_STGB)  // 90112

// out: block 64m x 256n, warps 2(m)x4(n), warp tile 32x64
#define O_ROWB 528
#define O_STGB (32*O_ROWB)             // 16896
#define OUT_B_OFF (4*A_STGB)           // 20480
#define OUT_SMEM  (OUT_B_OFF + 4*O_STGB)  // 88064

// aft: block 64t x 128d, warps 2(t)x4(d), warp tile 32x32 (dual acc)
#define AW_OFF  0
#define AE_OFF  (4*A_STGB)             // 20480
#define AV_OFF  (AE_OFF + 4*B_STGB)    // 55296
#define AFT_SMEM (AV_OFF + 4*B_STGB)   // 90112

// ---------------------------------------------------------------------------
// Fused K+V projection
// ---------------------------------------------------------------------------
__global__ __launch_bounds__(256, 2)
void kv_h(const float* __restrict__ bkb, const float* __restrict__ bvb)
{
    extern __shared__ char smc[];
    const uint32_t sb = smem_u32(smc);

    const int tid  = threadIdx.x;
    const int lane = tid & 31;
    const int warp = tid >> 5;
    const int wm   = warp >> 2;
    const int wn   = warp & 3;
    const int r    = lane >> 2;
    const int cc   = lane & 3;

    const int bm = blockIdx.y << 6;
    const int bn = blockIdx.x << 7;

    const int arow = tid >> 2;
    const int ac8  = (tid & 3) << 3;
    const int br0  = tid >> 4;
    const int bc8  = (tid & 15) << 3;

    const __half* Abase = g_xh  + (size_t)bm * DIM;
    const __half* Kbase = g_wkh + bn;
    const __half* Vbase = g_wvh + bn;

    const uint32_t aAddr   = sb + arow * A_ROWB + ac8 * 2;
    const uint32_t bkAddr0 = sb + KV_BK_OFF + br0 * B_ROWB + bc8 * 2;
    const uint32_t bvAddr0 = sb + KV_BV_OFF + br0 * B_ROWB + bc8 * 2;

    auto issue = [&](int c) {
        const int st = c & 3;
        const int k0 = c << 5;
        cp16(aAddr + st * A_STGB, Abase + (size_t)arow * DIM + k0 + ac8);
        #pragma unroll
        for (int j = 0; j < 2; j++) {
            const int row = br0 + (j << 4);
            cp16(bkAddr0 + (j << 4) * B_ROWB + st * B_STGB,
                 Kbase + (size_t)(k0 + row) * DIM + bc8);
            cp16(bvAddr0 + (j << 4) * B_ROWB + st * B_STGB,
                 Vbase + (size_t)(k0 + row) * DIM + bc8);
        }
        cp_commit();
    };

    float acck[2][4][4] = {};
    float accv[2][4][4] = {};

    issue(0); issue(1); issue(2);

    const int lrow = lane & 15;
    const int lk8  = (lane >> 4) << 3;

    for (int c = 0; c < 32; c++) {
        const int st = c & 3;
        cp_wait2();
        __syncthreads();
        if (c + 3 < 32) issue(c + 3);
        else cp_commit();

        const uint32_t Abuf = sb + st * A_STGB;
        const uint32_t Kbuf = sb + KV_BK_OFF + st * B_STGB;
        const uint32_t Vbuf = sb + KV_BV_OFF + st * B_STGB;

        #pragma unroll
        for (int ks = 0; ks < 2; ks++) {
            const int k0h = ks << 4;
            uint32_t af[2][4], bfk[2][4], bfv[2][4];
            #pragma unroll
            for (int im = 0; im < 2; im++) {
                const int m0 = (wm << 5) + (im << 4);
                ldsm_x4(af[im], Abuf + (m0 + lrow) * A_ROWB + (k0h + lk8) * 2);
            }
            #pragma unroll
            for (int ng = 0; ng < 2; ng++) {
                const int n0 = (wn << 5) + (ng << 4);
                ldsm_x4_t(bfk[ng], Kbuf + (k0h + lrow) * B_ROWB + (n0 + lk8) * 2);
                ldsm_x4_t(bfv[ng], Vbuf + (k0h + lrow) * B_ROWB + (n0 + lk8) * 2);
            }
            #pragma unroll
            for (int im = 0; im < 2; im++)
                #pragma unroll
                for (int ng = 0; ng < 2; ng++) {
                    mma_f16(acck[im][2*ng],   af[im][0], af[im][1], af[im][2], af[im][3],
                            bfk[ng][0], bfk[ng][1]);
                    mma_f16(acck[im][2*ng+1], af[im][0], af[im][1], af[im][2], af[im][3],
                            bfk[ng][2], bfk[ng][3]);
                    mma_f16(accv[im][2*ng],   af[im][0], af[im][1], af[im][2], af[im][3],
                            bfv[ng][0], bfv[ng][1]);
                    mma_f16(accv[im][2*ng+1], af[im][0], af[im][1], af[im][2], af[im][3],
                            bfv[ng][2], bfv[ng][3]);
                }
        }
    }

    #pragma unroll
    for (int im = 0; im < 2; im++) {
        #pragma unroll
        for (int in = 0; in < 4; in++) {
            #pragma unroll
            for (int e = 0; e < 4; e++) {
                const int row = bm + (wm << 5) + (im << 4) + r + ((e >> 1) << 3);
                const int col = bn + (wn << 5) + (in << 3) + (cc << 1) + (e & 1);
                const float kv = acck[im][in][e] + bkb[col];
                const float vv = accv[im][in][e] + bvb[col];
                const float ek = __expf(kv);
                const int n = row >> 11, s = row & (SEQ - 1);
                const int h = col >> 7, d = col & 127;
                const size_t idx = (((size_t)(n * HEADS + h)) * SEQ + s) * HD + d;
                g_ekh[idx]  = __float2half_rn(ek);
                g_ekvh[idx] = __float2half_rn(ek * vv);
            }
        }
    }
}

// ---------------------------------------------------------------------------
// Output projection: block 64m x 256n, warp tile 32x64.
// ---------------------------------------------------------------------------
__global__ __launch_bounds__(256, 2)
void out_h(const float* __restrict__ bias, float* __restrict__ out)
{
    extern __shared__ char smc[];
    const uint32_t sb = smem_u32(smc);

    const int tid  = threadIdx.x;
    const int lane = tid & 31;
    const int warp = tid >> 5;
    const int wm   = warp >> 2;
    const int wn   = warp & 3;
    const int r    = lane >> 2;
    const int cc   = lane & 3;

    const int bm = blockIdx.y << 6;
    const int bn = blockIdx.x << 8;

    const int arow = tid >> 2;
    const int ac8  = (tid & 3) << 3;
    const int br0  = tid >> 5;           // 0..7
    const int bc8  = (tid & 31) << 3;    // 0..248

    const __half* Abase = g_afth + (size_t)bm * DIM;
    const __half* Wbase = g_woh + bn;

    const uint32_t aAddr  = sb + arow * A_ROWB + ac8 * 2;
    const uint32_t bAddr0 = sb + OUT_B_OFF + br0 * O_ROWB + bc8 * 2;

    auto issue = [&](int c) {
        const int st = c & 3;
        const int k0 = c << 5;
        cp16(aAddr + st * A_STGB, Abase + (size_t)arow * DIM + k0 + ac8);
        #pragma unroll
        for (int j = 0; j < 4; j++) {
            const int row = br0 + (j << 3);
            cp16(bAddr0 + (j << 3) * O_ROWB + st * O_STGB,
                 Wbase + (size_t)(k0 + row) * DIM + bc8);
        }
        cp_commit();
    };

    float acc[2][8][4] = {};

    issue(0); issue(1); issue(2);

    const int lrow = lane & 15;
    const int lk8  = (lane >> 4) << 3;

    for (int c = 0; c < 32; c++) {
        const int st = c & 3;
        cp_wait2();
        __syncthreads();
        if (c + 3 < 32) issue(c + 3);
        else cp_commit();

        const uint32_t Abuf = sb + st * A_STGB;
        const uint32_t Bbuf = sb + OUT_B_OFF + st * O_STGB;

        #pragma unroll
        for (int ks = 0; ks < 2; ks++) {
            const int k0h = ks << 4;
            uint32_t af[2][4], bf[4][4];
            #pragma unroll
            for (int im = 0; im < 2; im++) {
                const int m0 = (wm << 5) + (im << 4);
                ldsm_x4(af[im], Abuf + (m0 + lrow) * A_ROWB + (k0h + lk8) * 2);
            }
            #pragma unroll
            for (int ng = 0; ng < 4; ng++) {
                const int n0 = (wn << 6) + (ng << 4);
                ldsm_x4_t(bf[ng], Bbuf + (k0h + lrow) * O_ROWB + (n0 + lk8) * 2);
            }
            #pragma unroll
            for (int im = 0; im < 2; im++)
                #pragma unroll
                for (int ng = 0; ng < 4; ng++) {
                    mma_f16(acc[im][2*ng],   af[im][0], af[im][1], af[im][2], af[im][3],
                            bf[ng][0], bf[ng][1]);
                    mma_f16(acc[im][2*ng+1], af[im][0], af[im][1], af[im][2], af[im][3],
                            bf[ng][2], bf[ng][3]);
                }
        }
    }

    #pragma unroll
    for (int im = 0; im < 2; im++) {
        #pragma unroll
        for (int in = 0; in < 8; in++) {
            #pragma unroll
            for (int e = 0; e < 4; e++) {
                const int row = bm + (wm << 5) + (im << 4) + r + ((e >> 1) << 3);
                const int col = bn + (wn << 6) + (in << 3) + (cc << 1) + (e & 1);
                out[(size_t)row * DIM + col] = acc[im][in][e] + bias[col];
            }
        }
    }
}

// ---------------------------------------------------------------------------
// AFT core: block 64t x 128d, warps 2(t)x4(d), warp tile 32x32 dual-acc.
// All three operands (ew, ek, ekv) via 4-stage cp.async.cg; no exp in-loop.
// ---------------------------------------------------------------------------
__global__ __launch_bounds__(256, 2)
void aft_h(int dummy)
{
    extern __shared__ char smc[];
    const uint32_t sb = smem_u32(smc);

    const int tid  = threadIdx.x;
    const int lane = tid & 31;
    const int warp = tid >> 5;
    const int wm   = warp >> 2;
    const int wn   = warp & 3;
    const int r    = lane >> 2;
    const int cc   = lane & 3;

    const int bt = gridDim.x - 1 - blockIdx.x;   // heavy tiles first
    const int t0 = bt << 6;
    const int nh = blockIdx.y;
    const int n  = nh >> 3;
    const int h  = nh & 7;

    const __half* wbase  = g_ewh  + ((size_t)h * SEQ + t0) * SEQ;
    const __half* ekbase = g_ekh  + (size_t)nh * SEQ * HD;
    const __half* evbase = g_ekvh + (size_t)nh * SEQ * HD;

    const int w_tl  = tid >> 2;           // 0..63
    const int w_c8  = (tid & 3) << 3;
    const int e_sl0 = tid >> 4;           // 0..15
    const int e_d8  = (tid & 15) << 3;

    const uint32_t wAddr   = sb + AW_OFF + w_tl * A_ROWB + w_c8 * 2;
    const uint32_t ekAddr0 = sb + AE_OFF + e_sl0 * B_ROWB + e_d8 * 2;
    const uint32_t evAddr0 = sb + AV_OFF + e_sl0 * B_ROWB + e_d8 * 2;

    auto issue = [&](int c) {
        const int st = c & 3;
        const int s0 = c << 5;
        cp16(wAddr + st * A_STGB, wbase + (size_t)w_tl * SEQ + s0 + w_c8);
        #pragma unroll
        for (int j = 0; j < 2; j++) {
            const int row = e_sl0 + (j << 4);
            cp16(ekAddr0 + (j << 4) * B_ROWB + st * B_STGB,
                 ekbase + (size_t)(s0 + row) * HD + e_d8);
            cp16(evAddr0 + (j << 4) * B_ROWB + st * B_STGB,
                 evbase + (size_t)(s0 + row) * HD + e_d8);
        }
        cp_commit();
    };

    float accN[2][4][4] = {};
    float accD[2][4][4] = {};

    const int nch = (bt + 1) << 1;    // s-chunks of 32 through diagonal
    issue(0); issue(1); issue(2);

    const int lrow = lane & 15;
    const int lk8  = (lane >> 4) << 3;

    for (int c = 0; c < nch; c++) {
        const int st = c & 3;
        cp_wait2();
        __syncthreads();
        if (c + 3 < nch) issue(c + 3);
        else cp_commit();

        const uint32_t Wbuf = sb + AW_OFF + st * A_STGB;
        const uint32_t Kbuf = sb + AE_OFF + st * B_STGB;
        const uint32_t Vbuf = sb + AV_OFF + st * B_STGB;

        #pragma unroll
        for (int ks = 0; ks < 2; ks++) {
            const int k0h = ks << 4;
            uint32_t af[2][4], bk[2][4], bv[2][4];
            #pragma unroll
            for (int im = 0; im < 2; im++) {
                const int m0 = (wm << 5) + (im << 4);
                ldsm_x4(af[im], Wbuf + (m0 + lrow) * A_ROWB + (k0h + lk8) * 2);
            }
            #pragma unroll
            for (int ng = 0; ng < 2; ng++) {
                const int n0 = (wn << 5) + (ng << 4);
                ldsm_x4_t(bk[ng], Kbuf + (k0h + lrow) * B_ROWB + (n0 + lk8) * 2);
                ldsm_x4_t(bv[ng], Vbuf + (k0h + lrow) * B_ROWB + (n0 + lk8) * 2);
            }
            #pragma unroll
            for (int im = 0; im < 2; im++)
                #pragma unroll
                for (int ng = 0; ng < 2; ng++) {
                    mma_f16(accN[im][2*ng],   af[im][0], af[im][1], af[im][2], af[im][3],
                            bv[ng][0], bv[ng][1]);
                    mma_f16(accN[im][2*ng+1], af[im][0], af[im][1], af[im][2], af[im][3],
                            bv[ng][2], bv[ng][3]);
                    mma_f16(accD[im][2*ng],   af[im][0], af[im][1], af[im][2], af[im][3],
                            bk[ng][0], bk[ng][1]);
                    mma_f16(accD[im][2*ng+1], af[im][0], af[im][1], af[im][2], af[im][3],
                            bk[ng][2], bk[ng][3]);
                }
        }
    }

    #pragma unroll
    for (int im = 0; im < 2; im++) {
        #pragma unroll
        for (int in = 0; in < 4; in++) {
            #pragma unroll
            for (int e = 0; e < 4; e++) {
                const int t = t0 + (wm << 5) + (im << 4) + r + ((e >> 1) << 3);
                const int d = (wn << 5) + (in << 3) + (cc << 1) + (e & 1);
                g_afth[((size_t)(n * SEQ + t)) * DIM + h * HD + d] =
                    __float2half_rn(__fdividef(accN[im][in][e], accD[im][in][e]));
            }
        }
    }
}

extern "C" void kernel_launch(void* const* d_in, const int* in_sizes, int n_in,
                              void* d_out, int out_size)
{
    const float* x     = (const float*)d_in[0];
    const float* Wk    = (const float*)d_in[1];
    const float* bk    = (const float*)d_in[2];
    const float* Wv    = (const float*)d_in[3];
    const float* bv    = (const float*)d_in[4];
    const float* w_aft = (const float*)d_in[5];
    const float* Wo    = (const float*)d_in[6];
    const float* bo    = (const float*)d_in[7];
    float* out = (float*)d_out;

    cudaFuncSetAttribute(kv_h,  cudaFuncAttributeMaxDynamicSharedMemorySize, KV_SMEM);
    cudaFuncSetAttribute(out_h, cudaFuncAttributeMaxDynamicSharedMemorySize, OUT_SMEM);
    cudaFuncSetAttribute(aft_h, cudaFuncAttributeMaxDynamicSharedMemorySize, AFT_SMEM);

    prep_all<<<PREP_BLOCKS, 256>>>((const float4*)x, (const float4*)Wk,
                                   (const float4*)Wv, (const float4*)Wo,
                                   (const float4*)w_aft);

    kv_h <<<dim3(DIM / 128, MROWS / 64), 256, KV_SMEM>>>(bk, bv);
    aft_h<<<dim3(SEQ / 64, NB * HEADS), 256, AFT_SMEM>>>(0);
    out_h<<<dim3(DIM / 256, MROWS / 64), 256, OUT_SMEM>>>(bo, out);
}

// round 13
// speedup vs baseline: 2.4792x; 1.0365x over previous
#include <cuda_runtime.h>
#include <cuda_fp16.h>
#include <cstdint>

#define NB    4
#define SEQ   2048
#define DIM   1024
#define HEADS 8
#define HD    128
#define MROWS (NB*SEQ)

// Scratch (device globals — no allocation allowed)
__device__ __half g_ekh [(size_t)NB*HEADS*SEQ*HD];     // exp(k), half
__device__ __half g_ekvh[(size_t)NB*HEADS*SEQ*HD];     // exp(k)*v, half
__device__ __half g_afth[(size_t)MROWS*DIM];           // AFT output, half
__device__ __half g_xh  [(size_t)MROWS*DIM];           // x, half
__device__ __half g_wkh [(size_t)DIM*DIM];             // weights [k][n], half
__device__ __half g_wvh [(size_t)DIM*DIM];
__device__ __half g_woh [(size_t)DIM*DIM];
__device__ __half g_ewh [(size_t)HEADS*SEQ*SEQ];       // exp(w_aft), causal-masked, half

// ---------------------------------------------------------------------------
// helpers
// ---------------------------------------------------------------------------
__device__ __forceinline__ void mma_f16(float c[4],
    uint32_t a0, uint32_t a1, uint32_t a2, uint32_t a3,
    uint32_t b0, uint32_t b1)
{
    asm volatile(
        "mma.sync.aligned.m16n8k16.row.col.f32.f16.f16.f32 "
        "{%0,%1,%2,%3}, {%4,%5,%6,%7}, {%8,%9}, {%0,%1,%2,%3};\n"
        : "+f"(c[0]), "+f"(c[1]), "+f"(c[2]), "+f"(c[3])
        : "r"(a0), "r"(a1), "r"(a2), "r"(a3), "r"(b0), "r"(b1));
}

__device__ __forceinline__ void ldsm_x4(uint32_t r[4], uint32_t addr) {
    asm volatile("ldmatrix.sync.aligned.m8n8.x4.shared.b16 {%0,%1,%2,%3}, [%4];\n"
        : "=r"(r[0]), "=r"(r[1]), "=r"(r[2]), "=r"(r[3]) : "r"(addr));
}
__device__ __forceinline__ void ldsm_x4_t(uint32_t r[4], uint32_t addr) {
    asm volatile("ldmatrix.sync.aligned.m8n8.x4.trans.shared.b16 {%0,%1,%2,%3}, [%4];\n"
        : "=r"(r[0]), "=r"(r[1]), "=r"(r[2]), "=r"(r[3]) : "r"(addr));
}

__device__ __forceinline__ uint32_t smem_u32(const void* p) {
    return (uint32_t)__cvta_generic_to_shared(p);
}
// .cg: bypass L1 — tiles are streamed once; keep L1 port for ldmatrix
__device__ __forceinline__ void cp16(uint32_t dst, const void* src) {
    asm volatile("cp.async.cg.shared.global [%0], [%1], 16;\n" :: "r"(dst), "l"(src));
}
__device__ __forceinline__ void cp_commit() {
    asm volatile("cp.async.commit_group;\n");
}
__device__ __forceinline__ void cp_wait0() {
    asm volatile("cp.async.wait_group 0;\n");
}

__device__ __forceinline__ uint32_t pack_h2(float a, float b) {
    __half2 h = __floats2half2_rn(a, b);
    return *reinterpret_cast<uint32_t*>(&h);
}

// ---------------------------------------------------------------------------
// prep: rounds x + 3 weights to fp16 AND builds causal exp(w_aft) fp16 table.
// ---------------------------------------------------------------------------
#define X8  ((size_t)MROWS*DIM/8)             // 1048576
#define W8  ((size_t)DIM*DIM/8)               // 131072
#define EW8 ((size_t)HEADS*SEQ*SEQ/8)         // 4194304
#define PREP_GROUPS (X8 + 3*W8 + EW8)
#define PREP_BLOCKS (PREP_GROUPS/256)         // 22016

__global__ __launch_bounds__(256)
void prep_all(const float4* __restrict__ x, const float4* __restrict__ wk,
              const float4* __restrict__ wv, const float4* __restrict__ wo,
              const float4* __restrict__ w_aft)
{
    size_t i = (size_t)blockIdx.x * 256 + threadIdx.x;
    if (i < X8 + 3*W8) {
        const float4* src;
        uint4* dst;
        if (i < X8) {
            src = x + i * 2;
            dst = (uint4*)g_xh + i;
        } else {
            size_t j = i - X8;
            int seg = (int)(j / W8);
            size_t o = j % W8;
            src = (seg == 0 ? wk : (seg == 1 ? wv : wo)) + o * 2;
            dst = (uint4*)(seg == 0 ? g_wkh : (seg == 1 ? g_wvh : g_woh)) + o;
        }
        float4 a = src[0], b = src[1];
        uint4 u;
        u.x = pack_h2(a.x, a.y); u.y = pack_h2(a.z, a.w);
        u.z = pack_h2(b.x, b.y); u.w = pack_h2(b.z, b.w);
        *dst = u;
    } else {
        size_t j = i - X8 - 3*W8;
        const size_t base = j * 8;
        const int s0 = (int)(base & (SEQ - 1));
        const int t  = (int)((base >> 11) & (SEQ - 1));
        float4 a = w_aft[j * 2], b = w_aft[j * 2 + 1];
        float e[8];
        e[0] = (s0 + 0 <= t) ? __expf(a.x) : 0.f;
        e[1] = (s0 + 1 <= t) ? __expf(a.y) : 0.f;
        e[2] = (s0 + 2 <= t) ? __expf(a.z) : 0.f;
        e[3] = (s0 + 3 <= t) ? __expf(a.w) : 0.f;
        e[4] = (s0 + 4 <= t) ? __expf(b.x) : 0.f;
        e[5] = (s0 + 5 <= t) ? __expf(b.y) : 0.f;
        e[6] = (s0 + 6 <= t) ? __expf(b.z) : 0.f;
        e[7] = (s0 + 7 <= t) ? __expf(b.w) : 0.f;
        uint4 u;
        u.x = pack_h2(e[0], e[1]); u.y = pack_h2(e[2], e[3]);
        u.z = pack_h2(e[4], e[5]); u.w = pack_h2(e[6], e[7]);
        ((uint4*)g_ewh)[j] = u;
    }
}

// ---------------------------------------------------------------------------
// Tiling: BK=64, 2-stage, one barrier per chunk.
// ---------------------------------------------------------------------------
#define A2_ROWB 144            // 64 halfs + 8 pad
#define A2_STGB (64*A2_ROWB)   // 9216
#define B2_ROWB 272            // 128 halfs + 8 pad
#define B2_STGB (64*B2_ROWB)   // 17408
#define O2_ROWB 528            // 256 halfs + 8 pad
#define O2_STGB (64*O2_ROWB)   // 33792

// kv: block 64m x 128n, warps 2(m)x4(n), warp tile 32x32 dual acc
#define KV_BK_OFF (2*A2_STGB)              // 18432
#define KV_BV_OFF (KV_BK_OFF + 2*B2_STGB)  // 53248
#define KV_SMEM   (KV_BV_OFF + 2*B2_STGB)  // 88064

// out: block 64m x 256n, warps 2(m)x4(n), warp tile 32x64
#define OUT_B_OFF (2*A2_STGB)              // 18432
#define OUT_SMEM  (OUT_B_OFF + 2*O2_STGB)  // 86016

// aft: block 64t x 128d, warps 2(t)x4(d), warp tile 32x32 dual acc
#define AE_OFF  (2*A2_STGB)                // 18432
#define AV_OFF  (AE_OFF + 2*B2_STGB)       // 53248
#define AFT_SMEM (AV_OFF + 2*B2_STGB)      // 88064

// ---------------------------------------------------------------------------
// Fused K+V projection
// ---------------------------------------------------------------------------
__global__ __launch_bounds__(256, 2)
void kv_h(const float* __restrict__ bkb, const float* __restrict__ bvb)
{
    extern __shared__ char smc[];
    const uint32_t sb = smem_u32(smc);

    const int tid  = threadIdx.x;
    const int lane = tid & 31;
    const int warp = tid >> 5;
    const int wm   = warp >> 2;
    const int wn   = warp & 3;
    const int r    = lane >> 2;
    const int cc   = lane & 3;

    const int bm = blockIdx.y << 6;
    const int bn = blockIdx.x << 7;

    // A: 512 cp16/chunk (2/thr): i = tid + j*256 -> row i>>3, half off (i&7)<<3
    // B: 1024 cp16/chunk each (4/thr): i -> row i>>4, half off (i&15)<<3
    const __half* Abase = g_xh  + (size_t)bm * DIM;
    const __half* Kbase = g_wkh + bn;
    const __half* Vbase = g_wvh + bn;

    auto issue = [&](int c) {
        const int st = c & 1;
        const int k0 = c << 6;
        #pragma unroll
        for (int j = 0; j < 2; j++) {
            const int i = tid + (j << 8);
            const int row = i >> 3, g8 = (i & 7) << 3;
            cp16(sb + st * A2_STGB + row * A2_ROWB + g8 * 2,
                 Abase + (size_t)row * DIM + k0 + g8);
        }
        #pragma unroll
        for (int j = 0; j < 4; j++) {
            const int i = tid + (j << 8);
            const int row = i >> 4, g8 = (i & 15) << 3;
            cp16(sb + KV_BK_OFF + st * B2_STGB + row * B2_ROWB + g8 * 2,
                 Kbase + (size_t)(k0 + row) * DIM + g8);
            cp16(sb + KV_BV_OFF + st * B2_STGB + row * B2_ROWB + g8 * 2,
                 Vbase + (size_t)(k0 + row) * DIM + g8);
        }
        cp_commit();
    };

    float acck[2][4][4] = {};
    float accv[2][4][4] = {};

    issue(0);

    const int lrow = lane & 15;
    const int lk8  = (lane >> 4) << 3;

    for (int c = 0; c < 16; c++) {
        cp_wait0();
        __syncthreads();
        if (c + 1 < 16) issue(c + 1);

        const int st = c & 1;
        const uint32_t Abuf = sb + st * A2_STGB;
        const uint32_t Kbuf = sb + KV_BK_OFF + st * B2_STGB;
        const uint32_t Vbuf = sb + KV_BV_OFF + st * B2_STGB;

        #pragma unroll
        for (int ks = 0; ks < 4; ks++) {
            const int k0h = ks << 4;
            uint32_t af[2][4], bfk[2][4], bfv[2][4];
            #pragma unroll
            for (int im = 0; im < 2; im++) {
                const int m0 = (wm << 5) + (im << 4);
                ldsm_x4(af[im], Abuf + (m0 + lrow) * A2_ROWB + (k0h + lk8) * 2);
            }
            #pragma unroll
            for (int ng = 0; ng < 2; ng++) {
                const int n0 = (wn << 5) + (ng << 4);
                ldsm_x4_t(bfk[ng], Kbuf + (k0h + lrow) * B2_ROWB + (n0 + lk8) * 2);
                ldsm_x4_t(bfv[ng], Vbuf + (k0h + lrow) * B2_ROWB + (n0 + lk8) * 2);
            }
            #pragma unroll
            for (int im = 0; im < 2; im++)
                #pragma unroll
                for (int ng = 0; ng < 2; ng++) {
                    mma_f16(acck[im][2*ng],   af[im][0], af[im][1], af[im][2], af[im][3],
                            bfk[ng][0], bfk[ng][1]);
                    mma_f16(acck[im][2*ng+1], af[im][0], af[im][1], af[im][2], af[im][3],
                            bfk[ng][2], bfk[ng][3]);
                    mma_f16(accv[im][2*ng],   af[im][0], af[im][1], af[im][2], af[im][3],
                            bfv[ng][0], bfv[ng][1]);
                    mma_f16(accv[im][2*ng+1], af[im][0], af[im][1], af[im][2], af[im][3],
                            bfv[ng][2], bfv[ng][3]);
                }
        }
    }

    #pragma unroll
    for (int im = 0; im < 2; im++) {
        #pragma unroll
        for (int in = 0; in < 4; in++) {
            #pragma unroll
            for (int e = 0; e < 4; e++) {
                const int row = bm + (wm << 5) + (im << 4) + r + ((e >> 1) << 3);
                const int col = bn + (wn << 5) + (in << 3) + (cc << 1) + (e & 1);
                const float kv = acck[im][in][e] + bkb[col];
                const float vv = accv[im][in][e] + bvb[col];
                const float ek = __expf(kv);
                const int n = row >> 11, s = row & (SEQ - 1);
                const int h = col >> 7, d = col & 127;
                const size_t idx = (((size_t)(n * HEADS + h)) * SEQ + s) * HD + d;
                g_ekh[idx]  = __float2half_rn(ek);
                g_ekvh[idx] = __float2half_rn(ek * vv);
            }
        }
    }
}

// ---------------------------------------------------------------------------
// Output projection: block 64m x 256n, warp tile 32x64.
// ---------------------------------------------------------------------------
__global__ __launch_bounds__(256, 2)
void out_h(const float* __restrict__ bias, float* __restrict__ out)
{
    extern __shared__ char smc[];
    const uint32_t sb = smem_u32(smc);

    const int tid  = threadIdx.x;
    const int lane = tid & 31;
    const int warp = tid >> 5;
    const int wm   = warp >> 2;
    const int wn   = warp & 3;
    const int r    = lane >> 2;
    const int cc   = lane & 3;

    const int bm = blockIdx.y << 6;
    const int bn = blockIdx.x << 8;

    const __half* Abase = g_afth + (size_t)bm * DIM;
    const __half* Wbase = g_woh + bn;

    auto issue = [&](int c) {
        const int st = c & 1;
        const int k0 = c << 6;
        #pragma unroll
        for (int j = 0; j < 2; j++) {
            const int i = tid + (j << 8);
            const int row = i >> 3, g8 = (i & 7) << 3;
            cp16(sb + st * A2_STGB + row * A2_ROWB + g8 * 2,
                 Abase + (size_t)row * DIM + k0 + g8);
        }
        #pragma unroll
        for (int j = 0; j < 8; j++) {
            const int i = tid + (j << 8);
            const int row = i >> 5, g8 = (i & 31) << 3;
            cp16(sb + OUT_B_OFF + st * O2_STGB + row * O2_ROWB + g8 * 2,
                 Wbase + (size_t)(k0 + row) * DIM + g8);
        }
        cp_commit();
    };

    float acc[2][8][4] = {};

    issue(0);

    const int lrow = lane & 15;
    const int lk8  = (lane >> 4) << 3;

    for (int c = 0; c < 16; c++) {
        cp_wait0();
        __syncthreads();
        if (c + 1 < 16) issue(c + 1);

        const int st = c & 1;
        const uint32_t Abuf = sb + st * A2_STGB;
        const uint32_t Bbuf = sb + OUT_B_OFF + st * O2_STGB;

        #pragma unroll
        for (int ks = 0; ks < 4; ks++) {
            const int k0h = ks << 4;
            uint32_t af[2][4], bf[4][4];
            #pragma unroll
            for (int im = 0; im < 2; im++) {
                const int m0 = (wm << 5) + (im << 4);
                ldsm_x4(af[im], Abuf + (m0 + lrow) * A2_ROWB + (k0h + lk8) * 2);
            }
            #pragma unroll
            for (int ng = 0; ng < 4; ng++) {
                const int n0 = (wn << 6) + (ng << 4);
                ldsm_x4_t(bf[ng], Bbuf + (k0h + lrow) * O2_ROWB + (n0 + lk8) * 2);
            }
            #pragma unroll
            for (int im = 0; im < 2; im++)
                #pragma unroll
                for (int ng = 0; ng < 4; ng++) {
                    mma_f16(acc[im][2*ng],   af[im][0], af[im][1], af[im][2], af[im][3],
                            bf[ng][0], bf[ng][1]);
                    mma_f16(acc[im][2*ng+1], af[im][0], af[im][1], af[im][2], af[im][3],
                            bf[ng][2], bf[ng][3]);
                }
        }
    }

    #pragma unroll
    for (int im = 0; im < 2; im++) {
        #pragma unroll
        for (int in = 0; in < 8; in++) {
            #pragma unroll
            for (int e = 0; e < 4; e++) {
                const int row = bm + (wm << 5) + (im << 4) + r + ((e >> 1) << 3);
                const int col = bn + (wn << 6) + (in << 3) + (cc << 1) + (e & 1);
                out[(size_t)row * DIM + col] = acc[im][in][e] + bias[col];
            }
        }
    }
}

// ---------------------------------------------------------------------------
// AFT core: block 64t x 128d, warps 2(t)x4(d), warp tile 32x32 dual-acc.
// s-chunks of 64, 2-stage, one barrier per chunk, heavy-first.
// ---------------------------------------------------------------------------
__global__ __launch_bounds__(256, 2)
void aft_h(int dummy)
{
    extern __shared__ char smc[];
    const uint32_t sb = smem_u32(smc);

    const int tid  = threadIdx.x;
    const int lane = tid & 31;
    const int warp = tid >> 5;
    const int wm   = warp >> 2;
    const int wn   = warp & 3;
    const int r    = lane >> 2;
    const int cc   = lane & 3;

    const int bt = gridDim.x - 1 - blockIdx.x;   // heavy tiles first
    const int t0 = bt << 6;
    const int nh = blockIdx.y;
    const int n  = nh >> 3;
    const int h  = nh & 7;

    const __half* wbase  = g_ewh  + ((size_t)h * SEQ + t0) * SEQ;
    const __half* ekbase = g_ekh  + (size_t)nh * SEQ * HD;
    const __half* evbase = g_ekvh + (size_t)nh * SEQ * HD;

    auto issue = [&](int c) {
        const int st = c & 1;
        const int s0 = c << 6;
        #pragma unroll
        for (int j = 0; j < 2; j++) {
            const int i = tid + (j << 8);
            const int row = i >> 3, g8 = (i & 7) << 3;   // row = t-local
            cp16(sb + st * A2_STGB + row * A2_ROWB + g8 * 2,
                 wbase + (size_t)row * SEQ + s0 + g8);
        }
        #pragma unroll
        for (int j = 0; j < 4; j++) {
            const int i = tid + (j << 8);
            const int row = i >> 4, g8 = (i & 15) << 3;  // row = s-local
            cp16(sb + AE_OFF + st * B2_STGB + row * B2_ROWB + g8 * 2,
                 ekbase + (size_t)(s0 + row) * HD + g8);
            cp16(sb + AV_OFF + st * B2_STGB + row * B2_ROWB + g8 * 2,
                 evbase + (size_t)(s0 + row) * HD + g8);
        }
        cp_commit();
    };

    float accN[2][4][4] = {};
    float accD[2][4][4] = {};

    const int nch = bt + 1;    // s-chunks of 64 through diagonal
    issue(0);

    const int lrow = lane & 15;
    const int lk8  = (lane >> 4) << 3;

    for (int c = 0; c < nch; c++) {
        cp_wait0();
        __syncthreads();
        if (c + 1 < nch) issue(c + 1);

        const int st = c & 1;
        const uint32_t Wbuf = sb + st * A2_STGB;
        const uint32_t Kbuf = sb + AE_OFF + st * B2_STGB;
        const uint32_t Vbuf = sb + AV_OFF + st * B2_STGB;

        #pragma unroll
        for (int ks = 0; ks < 4; ks++) {
            const int k0h = ks << 4;
            uint32_t af[2][4], bk[2][4], bv[2][4];
            #pragma unroll
            for (int im = 0; im < 2; im++) {
                const int m0 = (wm << 5) + (im << 4);
                ldsm_x4(af[im], Wbuf + (m0 + lrow) * A2_ROWB + (k0h + lk8) * 2);
            }
            #pragma unroll
            for (int ng = 0; ng < 2; ng++) {
                const int n0 = (wn << 5) + (ng << 4);
                ldsm_x4_t(bk[ng], Kbuf + (k0h + lrow) * B2_ROWB + (n0 + lk8) * 2);
                ldsm_x4_t(bv[ng], Vbuf + (k0h + lrow) * B2_ROWB + (n0 + lk8) * 2);
            }
            #pragma unroll
            for (int im = 0; im < 2; im++)
                #pragma unroll
                for (int ng = 0; ng < 2; ng++) {
                    mma_f16(accN[im][2*ng],   af[im][0], af[im][1], af[im][2], af[im][3],
                            bv[ng][0], bv[ng][1]);
                    mma_f16(accN[im][2*ng+1], af[im][0], af[im][1], af[im][2], af[im][3],
                            bv[ng][2], bv[ng][3]);
                    mma_f16(accD[im][2*ng],   af[im][0], af[im][1], af[im][2], af[im][3],
                            bk[ng][0], bk[ng][1]);
                    mma_f16(accD[im][2*ng+1], af[im][0], af[im][1], af[im][2], af[im][3],
                            bk[ng][2], bk[ng][3]);
                }
        }
    }

    #pragma unroll
    for (int im = 0; im < 2; im++) {
        #pragma unroll
        for (int in = 0; in < 4; in++) {
            #pragma unroll
            for (int e = 0; e < 4; e++) {
                const int t = t0 + (wm << 5) + (im << 4) + r + ((e >> 1) << 3);
                const int d = (wn << 5) + (in << 3) + (cc << 1) + (e & 1);
                g_afth[((size_t)(n * SEQ + t)) * DIM + h * HD + d] =
                    __float2half_rn(__fdividef(accN[im][in][e], accD[im][in][e]));
            }
        }
    }
}

extern "C" void kernel_launch(void* const* d_in, const int* in_sizes, int n_in,
                              void* d_out, int out_size)
{
    const float* x     = (const float*)d_in[0];
    const float* Wk    = (const float*)d_in[1];
    const float* bk    = (const float*)d_in[2];
    const float* Wv    = (const float*)d_in[3];
    const float* bv    = (const float*)d_in[4];
    const float* w_aft = (const float*)d_in[5];
    const float* Wo    = (const float*)d_in[6];
    const float* bo    = (const float*)d_in[7];
    float* out = (float*)d_out;

    cudaFuncSetAttribute(kv_h,  cudaFuncAttributeMaxDynamicSharedMemorySize, KV_SMEM);
    cudaFuncSetAttribute(out_h, cudaFuncAttributeMaxDynamicSharedMemorySize, OUT_SMEM);
    cudaFuncSetAttribute(aft_h, cudaFuncAttributeMaxDynamicSharedMemorySize, AFT_SMEM);

    prep_all<<<PREP_BLOCKS, 256>>>((const float4*)x, (const float4*)Wk,
                                   (const float4*)Wv, (const float4*)Wo,
                                   (const float4*)w_aft);

    kv_h <<<dim3(DIM / 128, MROWS / 64), 256, KV_SMEM>>>(bk, bv);
    aft_h<<<dim3(SEQ / 64, NB * HEADS), 256, AFT_SMEM>>>(0);
    out_h<<<dim3(DIM / 256, MROWS / 64), 256, OUT_SMEM>>>(bo, out);
}